// round 12
// baseline (speedup 1.0000x reference)
#include <cuda_runtime.h>
#include <cuda_fp16.h>
#include <cstdint>
#include <math.h>

#define BATCH 4
#define CHN   512
#define HW    4096
#define EPSF  1e-5f

// ---------------- scratch (device globals; no allocations allowed) ----------
__device__ float g_CNt[BATCH * CHN * HW];               // norm(content)^T [b][n][c]
__device__ float g_SNt[BATCH * CHN * HW];               // norm(style)^T   [b][n][c]
__device__ float g_St [BATCH * CHN * HW];               // style^T         [b][n][c]
__device__ float g_F[BATCH * CHN * HW];                 // F_t [b][n][c]
__device__ float g_G[BATCH * CHN * HW];                 // G_t [b][n][c]
__device__ __half g_Hh16[BATCH * CHN * HW];             // H fp16 [b][c][m]
__device__ float g_O[BATCH * CHN * HW];                 // O_t [b][n][c]
__device__ float g_S[(size_t)BATCH * HW * HW];          // S   [b][n][m]
__device__ __half g_P16[(size_t)BATCH * HW * HW];       // softmax(S) fp16
__device__ float g_mean[2 * BATCH * CHN];
__device__ float g_rstd[2 * BATCH * CHN];

// ============================ helpers =======================================
__device__ __forceinline__ void mma_f16_f32(float* d, const uint32_t* a, const uint32_t* b) {
    asm volatile(
        "mma.sync.aligned.m16n8k16.row.col.f32.f16.f16.f32 "
        "{%0,%1,%2,%3}, {%4,%5,%6,%7}, {%8,%9}, {%0,%1,%2,%3};"
        : "+f"(d[0]), "+f"(d[1]), "+f"(d[2]), "+f"(d[3])
        : "r"(a[0]), "r"(a[1]), "r"(a[2]), "r"(a[3]), "r"(b[0]), "r"(b[1]));
}
__device__ __forceinline__ void mma_s8(int* d, const uint32_t* a, const uint32_t* b) {
    asm volatile(
        "mma.sync.aligned.m16n8k32.row.col.s32.s8.s8.s32 "
        "{%0,%1,%2,%3}, {%4,%5,%6,%7}, {%8,%9}, {%0,%1,%2,%3};"
        : "+r"(d[0]), "+r"(d[1]), "+r"(d[2]), "+r"(d[3])
        : "r"(a[0]), "r"(a[1]), "r"(a[2]), "r"(a[3]), "r"(b[0]), "r"(b[1]));
}

__device__ __forceinline__ void prep2(float x, float y, uint32_t& hpack,
                                      float& hx, float& hy) {
    __half a = __float2half_rn(x), b = __float2half_rn(y);
    __half2 h2 = __halves2half2(a, b);
    hpack = *(uint32_t*)&h2;
    hx = __half2float(a); hy = __half2float(b);
}
__device__ __forceinline__ int q8(float f, float s) {
    int q = __float2int_rn(f * s);
    return max(-127, min(127, q));
}
__device__ __forceinline__ uint32_t pack4b(int a, int b, int c, int d) {
    return (uint32_t)(a & 0xff) | ((uint32_t)(b & 0xff) << 8) |
           ((uint32_t)(c & 0xff) << 16) | ((uint32_t)(d & 0xff) << 24);
}

// ============ hybrid fp16 + int8-correction GEMM (NT), 256 threads =========
// D[m,n] = sum_k A[m,k]*B[n,k] (+bias/resid).
// Main term: fp16 Ah*Bh (fp32 acc). Corrections in int8 k32 IMMA, shared s32
// acc, scale 1/(iA*iB*2048): TERMS 3 = +AhBl+AlBh ; TERMS 2 = +AhBl only.
// 128x128 CTA tile, 8 warps (2x4), warp tile 64x32, BK=32, double-buffered.
#define HGK_FROW  20
#define HGK_FMAT  (128 * HGK_FROW)               // 2560 u32 per fp16 plane
#define HGK_QROW  12
#define HGK_QMAT  (128 * HGK_QROW)               // 1536 u32 per int8 plane
#define OFF_FA    0
#define OFF_FB    HGK_FMAT
#define OFF_QAH   (2 * HGK_FMAT)
#define OFF_QAL   (2 * HGK_FMAT + HGK_QMAT)
#define OFF_QBH   (2 * HGK_FMAT + 2 * HGK_QMAT)
#define OFF_QBL   (2 * HGK_FMAT + 3 * HGK_QMAT)
#define HGK_STAGE (2 * HGK_FMAT + 4 * HGK_QMAT)  // 11264 u32
#define HGK_SMEMB (2 * HGK_STAGE * 4)            // 90112 bytes

template<int BIASMODE, bool RESID, int TERMS, bool OUTHALF>
__global__ void __launch_bounds__(256, 1)
hyb_gemm_kernel(const float* __restrict__ Ag, const float* __restrict__ Bg,
                const float* __restrict__ bias, const float* __restrict__ residg,
                float* __restrict__ Cg, __half* __restrict__ Chg,
                int K, int ldA, int ldB, int ldC,
                size_t sA, size_t sB, size_t sC,
                float iA, float iB, float cscale)
{
    extern __shared__ uint32_t smem_u32[];

    const int t    = threadIdx.x;
    const int lane = t & 31;
    const int wid  = t >> 5;
    const int wm   = wid >> 2;          // 0..1 (64-row band)
    const int wn   = wid & 3;           // 0..3 (32-col band)
    const int r0   = lane >> 2;         // 0..7
    const int c0   = lane & 3;          // 0..3

    const int b  = blockIdx.z;
    const int m0 = blockIdx.y * 128, n0 = blockIdx.x * 128;
    const float* A = Ag + (size_t)b * sA + (size_t)m0 * ldA;
    const float* B = Bg + (size_t)b * sB + (size_t)n0 * ldB;

    const int NC = K >> 5;
    const int lrow = t >> 1;            // 0..127
    const int half = t & 1;             // k-half (0 or 16)
    const float iA2 = iA * 2048.0f, iB2 = iB * 2048.0f;

    float4 va[4], vb[4];

    auto gload = [&](int c) {
        const int k0 = (c << 5) + half * 16;
        #pragma unroll
        for (int j = 0; j < 4; j++) {
            va[j] = *(const float4*)&A[(size_t)lrow * ldA + k0 + j * 4];
            vb[j] = *(const float4*)&B[(size_t)lrow * ldB + k0 + j * 4];
        }
    };
    auto sstore = [&](int s) {
        uint32_t* st = smem_u32 + s * HGK_STAGE;
        uint32_t qh[4], ql[4];
        // ---- A ----
        #pragma unroll
        for (int j = 0; j < 4; j++) {
            float4 v = va[j];
            uint32_t h01, h23; float hx, hy, hz, hw;
            prep2(v.x, v.y, h01, hx, hy);
            prep2(v.z, v.w, h23, hz, hw);
            st[OFF_FA + lrow * HGK_FROW + half * 8 + j * 2]     = h01;
            st[OFF_FA + lrow * HGK_FROW + half * 8 + j * 2 + 1] = h23;
            qh[j] = pack4b(q8(hx, iA), q8(hy, iA), q8(hz, iA), q8(hw, iA));
            if (TERMS == 3)
                ql[j] = pack4b(q8(v.x - hx, iA2), q8(v.y - hy, iA2),
                               q8(v.z - hz, iA2), q8(v.w - hw, iA2));
        }
        *(uint4*)&st[OFF_QAH + lrow * HGK_QROW + half * 4] =
            make_uint4(qh[0], qh[1], qh[2], qh[3]);
        if (TERMS == 3)
            *(uint4*)&st[OFF_QAL + lrow * HGK_QROW + half * 4] =
                make_uint4(ql[0], ql[1], ql[2], ql[3]);
        // ---- B ----
        #pragma unroll
        for (int j = 0; j < 4; j++) {
            float4 v = vb[j];
            uint32_t h01, h23; float hx, hy, hz, hw;
            prep2(v.x, v.y, h01, hx, hy);
            prep2(v.z, v.w, h23, hz, hw);
            st[OFF_FB + lrow * HGK_FROW + half * 8 + j * 2]     = h01;
            st[OFF_FB + lrow * HGK_FROW + half * 8 + j * 2 + 1] = h23;
            if (TERMS == 3)
                qh[j] = pack4b(q8(hx, iB), q8(hy, iB), q8(hz, iB), q8(hw, iB));
            ql[j] = pack4b(q8(v.x - hx, iB2), q8(v.y - hy, iB2),
                           q8(v.z - hz, iB2), q8(v.w - hw, iB2));
        }
        if (TERMS == 3)
            *(uint4*)&st[OFF_QBH + lrow * HGK_QROW + half * 4] =
                make_uint4(qh[0], qh[1], qh[2], qh[3]);
        *(uint4*)&st[OFF_QBL + lrow * HGK_QROW + half * 4] =
            make_uint4(ql[0], ql[1], ql[2], ql[3]);
    };

    float acc[4][4][4] = {};
    int  sacc[4][4][4] = {};

    gload(0);
    sstore(0);
    if (NC > 1) gload(1);
    __syncthreads();

    for (int c = 0; c < NC; c++) {
        const int s = c & 1;
        const uint32_t* stg = smem_u32 + s * HGK_STAGE;
        const uint32_t* fA  = stg + OFF_FA;
        const uint32_t* fB  = stg + OFF_FB;

        // ---- fp16 main term (2 kk sub-chunks) ----
        #pragma unroll
        for (int kk = 0; kk < 2; kk++) {
            uint32_t ah[4][4], bh[4][2];
            const int cA = kk * 8 + c0;
            #pragma unroll
            for (int mt = 0; mt < 4; mt++) {
                int r = wm * 64 + mt * 16 + r0;
                const uint32_t* p = &fA[r * HGK_FROW + cA];
                ah[mt][0] = p[0]; ah[mt][1] = p[8 * HGK_FROW];
                ah[mt][2] = p[4]; ah[mt][3] = p[8 * HGK_FROW + 4];
            }
            #pragma unroll
            for (int nt = 0; nt < 4; nt++) {
                int n = wn * 32 + nt * 8 + r0;
                bh[nt][0] = fB[n * HGK_FROW + cA];
                bh[nt][1] = fB[n * HGK_FROW + cA + 4];
            }
            if (kk == 0) { if (c + 1 < NC) sstore((c + 1) & 1); }
            else         { if (c + 2 < NC) gload(c + 2); }
            #pragma unroll
            for (int mt = 0; mt < 4; mt++)
                #pragma unroll
                for (int nt = 0; nt < 4; nt++)
                    mma_f16_f32(acc[mt][nt], ah[mt], bh[nt]);
        }

        // ---- int8 corrections (one IMMA covers full 32-k chunk) ----
        {
            uint32_t qa[4][4], qb[4][2];
            const uint32_t* qAh = stg + OFF_QAH;
            const uint32_t* qBl = stg + OFF_QBL;
            #pragma unroll
            for (int mt = 0; mt < 4; mt++) {
                int r = wm * 64 + mt * 16 + r0;
                const uint32_t* p = &qAh[r * HGK_QROW + c0];
                qa[mt][0] = p[0]; qa[mt][1] = p[8 * HGK_QROW];
                qa[mt][2] = p[4]; qa[mt][3] = p[8 * HGK_QROW + 4];
            }
            #pragma unroll
            for (int nt = 0; nt < 4; nt++) {
                int n = wn * 32 + nt * 8 + r0;
                qb[nt][0] = qBl[n * HGK_QROW + c0];
                qb[nt][1] = qBl[n * HGK_QROW + c0 + 4];
            }
            #pragma unroll
            for (int mt = 0; mt < 4; mt++)
                #pragma unroll
                for (int nt = 0; nt < 4; nt++)
                    mma_s8(sacc[mt][nt], qa[mt], qb[nt]);

            if (TERMS == 3) {
                const uint32_t* qAl = stg + OFF_QAL;
                const uint32_t* qBh = stg + OFF_QBH;
                #pragma unroll
                for (int mt = 0; mt < 4; mt++) {
                    int r = wm * 64 + mt * 16 + r0;
                    const uint32_t* p = &qAl[r * HGK_QROW + c0];
                    qa[mt][0] = p[0]; qa[mt][1] = p[8 * HGK_QROW];
                    qa[mt][2] = p[4]; qa[mt][3] = p[8 * HGK_QROW + 4];
                }
                #pragma unroll
                for (int nt = 0; nt < 4; nt++) {
                    int n = wn * 32 + nt * 8 + r0;
                    qb[nt][0] = qBh[n * HGK_QROW + c0];
                    qb[nt][1] = qBh[n * HGK_QROW + c0 + 4];
                }
                #pragma unroll
                for (int mt = 0; mt < 4; mt++)
                    #pragma unroll
                    for (int nt = 0; nt < 4; nt++)
                        mma_s8(sacc[mt][nt], qa[mt], qb[nt]);
            }
        }
        __syncthreads();
    }

    // ---- epilogue: fold corrections, bias, resid ----
    #pragma unroll
    for (int mt = 0; mt < 4; mt++) {
        int row = m0 + wm * 64 + mt * 16 + r0;
        float br0 = 0.f, br1 = 0.f;
        if (BIASMODE == 1) { br0 = bias[row]; br1 = bias[row + 8]; }
        #pragma unroll
        for (int nt = 0; nt < 4; nt++) {
            int col = n0 + wn * 32 + nt * 8 + c0 * 2;
            float2 v0, v1;
            v0.x = acc[mt][nt][0] + (float)sacc[mt][nt][0] * cscale;
            v0.y = acc[mt][nt][1] + (float)sacc[mt][nt][1] * cscale;
            v1.x = acc[mt][nt][2] + (float)sacc[mt][nt][2] * cscale;
            v1.y = acc[mt][nt][3] + (float)sacc[mt][nt][3] * cscale;
            if (BIASMODE == 1) {
                v0.x += br0; v0.y += br0;
                v1.x += br1; v1.y += br1;
            } else if (BIASMODE == 2) {
                float bx = bias[col], by = bias[col + 1];
                v0.x += bx; v0.y += by;
                v1.x += bx; v1.y += by;
            }
            size_t o0 = (size_t)b * sC + (size_t)row * ldC + col;
            size_t o1 = (size_t)b * sC + (size_t)(row + 8) * ldC + col;
            if (OUTHALF) {
                *(__half2*)&Chg[o0] = __floats2half2_rn(v0.x, v0.y);
                *(__half2*)&Chg[o1] = __floats2half2_rn(v1.x, v1.y);
            } else {
                if (RESID) {
                    float2 rv0 = *(const float2*)&residg[o0];
                    float2 rv1 = *(const float2*)&residg[o1];
                    v0.x += rv0.x; v0.y += rv0.y;
                    v1.x += rv1.x; v1.y += rv1.y;
                }
                *(float2*)&Cg[o0] = v0;
                *(float2*)&Cg[o1] = v1;
            }
        }
    }
}

// ============ pure fp16 GEMM (NT): both operands fp16 in gmem ==============
#define BGK_ROW   20
#define PGK_MAT   (128 * BGK_ROW)
#define PGK_STAGE (2 * PGK_MAT)
#define PGK_SMEMB (2 * PGK_STAGE * 4)            // 40960 bytes

__global__ void __launch_bounds__(512, 1)
f16_pure_gemm_kernel(const __half* __restrict__ Ag, const __half* __restrict__ Bg,
                     float* __restrict__ Cg, int K, int ldA, int ldB, int ldC,
                     size_t sA, size_t sB, size_t sC)
{
    extern __shared__ uint32_t smem_u32[];

    const int t    = threadIdx.x;
    const int lane = t & 31;
    const int wid  = t >> 5;
    const int wm   = wid >> 2;
    const int wn   = wid & 3;
    const int r0   = lane >> 2;
    const int c0   = lane & 3;

    const int b  = blockIdx.z;
    const int m0 = blockIdx.y * 128, n0 = blockIdx.x * 128;
    const __half* A = Ag + (size_t)b * sA + (size_t)m0 * ldA;
    const __half* B = Bg + (size_t)b * sB + (size_t)n0 * ldB;
    float*        C = Cg + (size_t)b * sC;

    const int NC = K >> 5;
    const int lrow = t >> 2;
    const int lq   = t & 3;

    uint4 ua, ub;
    auto gload = [&](int c) {
        const int k0 = c << 5;
        ua = *(const uint4*)&A[(size_t)lrow * ldA + k0 + lq * 8];
        ub = *(const uint4*)&B[(size_t)lrow * ldB + k0 + lq * 8];
    };
    auto sstore = [&](int s) {
        uint32_t* base = smem_u32 + s * PGK_STAGE;
        *(uint4*)&base[lrow * BGK_ROW + lq * 4] = ua;
        *(uint4*)&base[PGK_MAT + lrow * BGK_ROW + lq * 4] = ub;
    };

    float acc[2][4][4] = {};

    gload(0);
    sstore(0);
    if (NC > 1) gload(1);
    __syncthreads();

    for (int c = 0; c < NC; c++) {
        const int s = c & 1;
        const uint32_t* sa = smem_u32 + s * PGK_STAGE;
        const uint32_t* sb = sa + PGK_MAT;

        #pragma unroll
        for (int kk = 0; kk < 2; kk++) {
            uint32_t ah[2][4], bh[4][2];
            const int cA = kk * 8 + c0;
            #pragma unroll
            for (int mt = 0; mt < 2; mt++) {
                int r = wm * 32 + mt * 16 + r0;
                const uint32_t* ph = &sa[r * BGK_ROW + cA];
                ah[mt][0] = ph[0]; ah[mt][1] = ph[8 * BGK_ROW];
                ah[mt][2] = ph[4]; ah[mt][3] = ph[8 * BGK_ROW + 4];
            }
            #pragma unroll
            for (int nt = 0; nt < 4; nt++) {
                int n = wn * 32 + nt * 8 + r0;
                bh[nt][0] = sb[n * BGK_ROW + cA]; bh[nt][1] = sb[n * BGK_ROW + cA + 4];
            }

            if (kk == 0) { if (c + 1 < NC) sstore((c + 1) & 1); }
            else         { if (c + 2 < NC) gload(c + 2); }

            #pragma unroll
            for (int mt = 0; mt < 2; mt++)
                #pragma unroll
                for (int nt = 0; nt < 4; nt++)
                    mma_f16_f32(acc[mt][nt], ah[mt], bh[nt]);
        }
        __syncthreads();
    }

    #pragma unroll
    for (int mt = 0; mt < 2; mt++) {
        int row = m0 + wm * 32 + mt * 16 + r0;
        #pragma unroll
        for (int nt = 0; nt < 4; nt++) {
            int col = n0 + wn * 32 + nt * 8 + c0 * 2;
            *(float2*)&C[(size_t)row * ldC + col] =
                make_float2(acc[mt][nt][0], acc[mt][nt][1]);
            *(float2*)&C[(size_t)(row + 8) * ldC + col] =
                make_float2(acc[mt][nt][2], acc[mt][nt][3]);
        }
    }
}

// ---------------- per-(b,c) mean / rstd over 4096 spatial elems -------------
__global__ void __launch_bounds__(256)
stats_kernel(const float* __restrict__ content, const float* __restrict__ style)
{
    int bc  = blockIdx.x;
    int sel = blockIdx.y;
    const float* x = (sel == 0 ? content : style) + (size_t)bc * HW;

    float s1 = 0.f, s2 = 0.f;
    for (int i = threadIdx.x * 4; i < HW; i += 256 * 4) {
        float4 v = *(const float4*)&x[i];
        s1 += v.x + v.y + v.z + v.w;
        s2 += v.x * v.x + v.y * v.y + v.z * v.z + v.w * v.w;
    }
    __shared__ float sh1[8], sh2[8];
    for (int o = 16; o > 0; o >>= 1) {
        s1 += __shfl_xor_sync(0xffffffffu, s1, o);
        s2 += __shfl_xor_sync(0xffffffffu, s2, o);
    }
    int warp = threadIdx.x >> 5, lane = threadIdx.x & 31;
    if (lane == 0) { sh1[warp] = s1; sh2[warp] = s2; }
    __syncthreads();
    if (threadIdx.x < 32) {
        s1 = (lane < 8) ? sh1[lane] : 0.f;
        s2 = (lane < 8) ? sh2[lane] : 0.f;
        for (int o = 4; o > 0; o >>= 1) {
            s1 += __shfl_xor_sync(0xffffffffu, s1, o);
            s2 += __shfl_xor_sync(0xffffffffu, s2, o);
        }
        if (lane == 0) {
            float mean = s1 / (float)HW;
            float var  = (s2 - s1 * mean) / (float)(HW - 1);
            int idx = sel * BATCH * CHN + bc;
            g_mean[idx] = mean;
            g_rstd[idx] = rsqrtf(var + EPSF);
        }
    }
}

// ------- transpose + normalize: [b][c][n] -> [b][n][c], 3 outputs ----------
__global__ void __launch_bounds__(256)
transnorm_kernel(const float* __restrict__ content, const float* __restrict__ style,
                 float* __restrict__ CNt, float* __restrict__ SNt,
                 float* __restrict__ St)
{
    __shared__ float tc[32][33], ts[32][33];
    int b  = blockIdx.z;
    int c0 = blockIdx.y * 32, n0 = blockIdx.x * 32;
    int t  = threadIdx.x;
    int r  = t >> 3, q = (t & 7) * 4;

    size_t ib = (size_t)b * CHN * HW + (size_t)(c0 + r) * HW + n0 + q;
    float mC = g_mean[b * CHN + c0 + r], rC = g_rstd[b * CHN + c0 + r];
    float4 v = *(const float4*)&content[ib];
    tc[r][q + 0] = (v.x - mC) * rC; tc[r][q + 1] = (v.y - mC) * rC;
    tc[r][q + 2] = (v.z - mC) * rC; tc[r][q + 3] = (v.w - mC) * rC;
    float4 w = *(const float4*)&style[ib];
    ts[r][q + 0] = w.x; ts[r][q + 1] = w.y; ts[r][q + 2] = w.z; ts[r][q + 3] = w.w;
    __syncthreads();

    size_t ob = (size_t)b * CHN * HW + (size_t)(n0 + r) * CHN + c0 + q;
    float4 o;
    o.x = tc[q + 0][r]; o.y = tc[q + 1][r]; o.z = tc[q + 2][r]; o.w = tc[q + 3][r];
    *(float4*)&CNt[ob] = o;

    float4 sraw;
    sraw.x = ts[q + 0][r]; sraw.y = ts[q + 1][r];
    sraw.z = ts[q + 2][r]; sraw.w = ts[q + 3][r];
    *(float4*)&St[ob] = sraw;

    int sidx = BATCH * CHN + b * CHN + c0 + q;
    float4 sm = *(const float4*)&g_mean[sidx];
    float4 sr = *(const float4*)&g_rstd[sidx];
    float4 sn;
    sn.x = (sraw.x - sm.x) * sr.x; sn.y = (sraw.y - sm.y) * sr.y;
    sn.z = (sraw.z - sm.z) * sr.z; sn.w = (sraw.w - sm.w) * sr.w;
    *(float4*)&SNt[ob] = sn;
}

// ------- row softmax over 4096, fp16 output ---------------------------------
__global__ void __launch_bounds__(256)
softmax_kernel(const float* __restrict__ S, __half* __restrict__ P16)
{
    __shared__ float buf[HW];
    __shared__ float red1[8], red2[8];
    const float* p = S + (size_t)blockIdx.x * HW;
    __half* po = P16 + (size_t)blockIdx.x * HW;
    int t = threadIdx.x, lane = t & 31, warp = t >> 5;

    float m = -3.4e38f;
    for (int i = t * 4; i < HW; i += 1024) {
        float4 v = *(const float4*)&p[i];
        *(float4*)&buf[i] = v;
        m = fmaxf(m, fmaxf(fmaxf(v.x, v.y), fmaxf(v.z, v.w)));
    }
    for (int o = 16; o > 0; o >>= 1) m = fmaxf(m, __shfl_xor_sync(0xffffffffu, m, o));
    if (lane == 0) red1[warp] = m;
    __syncthreads();
    if (t < 32) {
        m = (lane < 8) ? red1[lane] : -3.4e38f;
        for (int o = 4; o > 0; o >>= 1) m = fmaxf(m, __shfl_xor_sync(0xffffffffu, m, o));
        if (lane == 0) red1[0] = m;
    }
    __syncthreads();
    m = red1[0];

    float s = 0.f;
    for (int i = t * 4; i < HW; i += 1024) {
        float4 v = *(const float4*)&buf[i];
        v.x = __expf(v.x - m); v.y = __expf(v.y - m);
        v.z = __expf(v.z - m); v.w = __expf(v.w - m);
        *(float4*)&buf[i] = v;
        s += v.x + v.y + v.z + v.w;
    }
    for (int o = 16; o > 0; o >>= 1) s += __shfl_xor_sync(0xffffffffu, s, o);
    if (lane == 0) red2[warp] = s;
    __syncthreads();
    if (t < 32) {
        s = (lane < 8) ? red2[lane] : 0.f;
        for (int o = 4; o > 0; o >>= 1) s += __shfl_xor_sync(0xffffffffu, s, o);
        if (lane == 0) red2[0] = s;
    }
    __syncthreads();
    float inv = 1.0f / red2[0];
    for (int i = t * 4; i < HW; i += 1024) {
        float4 v = *(const float4*)&buf[i];
        *(__half2*)&po[i]     = __floats2half2_rn(v.x * inv, v.y * inv);
        *(__half2*)&po[i + 2] = __floats2half2_rn(v.z * inv, v.w * inv);
    }
}

// ---------------- launch --------------------------------------------------
extern "C" void kernel_launch(void* const* d_in, const int* in_sizes, int n_in,
                              void* d_out, int out_size)
{
    const float* content = (const float*)d_in[0];
    const float* style   = (const float*)d_in[1];
    const float* Wf = (const float*)d_in[2]; const float* bf = (const float*)d_in[3];
    const float* Wg = (const float*)d_in[4]; const float* bg = (const float*)d_in[5];
    const float* Wh = (const float*)d_in[6]; const float* bh = (const float*)d_in[7];
    const float* Wo = (const float*)d_in[8]; const float* bo = (const float*)d_in[9];
    float* out = (float*)d_out;

    float *pCNt, *pSNt, *pSt, *pF, *pG, *pO, *pS;
    __half *pH16, *pP16;
    cudaGetSymbolAddress((void**)&pCNt, g_CNt);
    cudaGetSymbolAddress((void**)&pSNt, g_SNt);
    cudaGetSymbolAddress((void**)&pSt,  g_St);
    cudaGetSymbolAddress((void**)&pF, g_F);
    cudaGetSymbolAddress((void**)&pG, g_G);
    cudaGetSymbolAddress((void**)&pH16, g_Hh16);
    cudaGetSymbolAddress((void**)&pO, g_O);
    cudaGetSymbolAddress((void**)&pS, g_S);
    cudaGetSymbolAddress((void**)&pP16, g_P16);

    cudaFuncSetAttribute(hyb_gemm_kernel<2, false, 3, false>,
                         cudaFuncAttributeMaxDynamicSharedMemorySize, HGK_SMEMB);
    cudaFuncSetAttribute(hyb_gemm_kernel<1, false, 2, true>,
                         cudaFuncAttributeMaxDynamicSharedMemorySize, HGK_SMEMB);
    cudaFuncSetAttribute(hyb_gemm_kernel<0, false, 3, false>,
                         cudaFuncAttributeMaxDynamicSharedMemorySize, HGK_SMEMB);
    cudaFuncSetAttribute(hyb_gemm_kernel<1, true, 2, false>,
                         cudaFuncAttributeMaxDynamicSharedMemorySize, HGK_SMEMB);
    cudaFuncSetAttribute(f16_pure_gemm_kernel,
                         cudaFuncAttributeMaxDynamicSharedMemorySize, PGK_SMEMB);

    const size_t sBCHW = (size_t)CHN * HW;
    const size_t sBHH  = (size_t)HW * HW;

    // int8 hi-scales: data (±~6) -> 16 ; weights (±~0.25) -> 512
    const float iDAT = 16.f, iWGT = 512.f;
    auto csc = [](float ia, float ib) { return 1.0f / (ia * ib * 2048.0f); };

    // 1) normalization stats
    stats_kernel<<<dim3(BATCH * CHN, 2), 256>>>(content, style);

    // 2) transpose + normalize: CN_t, SN_t, St  ([b][n][c])
    transnorm_kernel<<<dim3(HW / 32, CHN / 32, BATCH), 256>>>(
        content, style, pCNt, pSNt, pSt);

    // 3) F_t[n,c] = CN_t[n,:] . Wf[c,:]   (hybrid 3-term)
    hyb_gemm_kernel<2, false, 3, false><<<dim3(CHN / 128, HW / 128, BATCH), 256, HGK_SMEMB>>>(
        pCNt, Wf, bf, nullptr, pF, nullptr, CHN, CHN, CHN, CHN, sBCHW, 0, sBCHW,
        iDAT, iWGT, csc(iDAT, iWGT));

    // 4) G_t[n,c] = SN_t[n,:] . Wg[c,:]   (hybrid 3-term)
    hyb_gemm_kernel<2, false, 3, false><<<dim3(CHN / 128, HW / 128, BATCH), 256, HGK_SMEMB>>>(
        pSNt, Wg, bg, nullptr, pG, nullptr, CHN, CHN, CHN, CHN, sBCHW, 0, sBCHW,
        iDAT, iWGT, csc(iDAT, iWGT));

    // 5) H[c,m] = Wh[c,:] . St[m,:]       (hybrid 2-term; fp16 out)
    hyb_gemm_kernel<1, false, 2, true><<<dim3(HW / 128, CHN / 128, BATCH), 256, HGK_SMEMB>>>(
        Wh, pSt, bh, nullptr, nullptr, pH16, CHN, CHN, CHN, HW, 0, sBCHW, sBCHW,
        iWGT, iDAT, csc(iWGT, iDAT));

    // 6) S[n,m] = F_t[n,:] . G_t[m,:]     (hybrid 3-term; logits)
    hyb_gemm_kernel<0, false, 3, false><<<dim3(HW / 128, HW / 128, BATCH), 256, HGK_SMEMB>>>(
        pF, pG, nullptr, nullptr, pS, nullptr, CHN, CHN, CHN, HW,
        sBCHW, sBCHW, sBHH, iDAT, iDAT, csc(iDAT, iDAT));

    // 7) softmax rows of S -> fp16 P
    softmax_kernel<<<BATCH * HW, 256>>>(pS, pP16);

    // 8) O_t[n,c] = P[n,:] . H[c,:]       (pure fp16, 1 term)
    f16_pure_gemm_kernel<<<dim3(CHN / 128, HW / 128, BATCH), 512, PGK_SMEMB>>>(
        pP16, pH16, pO, HW, HW, HW, CHN, sBHH, sBCHW, sBCHW);

    // 9) out[c,n] = Wo[c,:] . O_t[n,:] + bo + content  (hybrid 2-term + resid)
    hyb_gemm_kernel<1, true, 2, false><<<dim3(HW / 128, CHN / 128, BATCH), 256, HGK_SMEMB>>>(
        Wo, pO, bo, content, out, nullptr, CHN, CHN, CHN, HW, 0, sBCHW, sBCHW,
        iWGT, iDAT, csc(iWGT, iDAT));
}

// round 14
// speedup vs baseline: 1.8349x; 1.8349x over previous
#include <cuda_runtime.h>
#include <cuda_fp16.h>
#include <cstdint>
#include <math.h>

#define BATCH 4
#define CHN   512
#define HW    4096
#define EPSF  1e-5f
#define WSZ   (CHN * CHN)

// ---------------- scratch (device globals; no allocations allowed) ----------
__device__ float g_CNt[BATCH * CHN * HW];               // norm(content)^T [b][n][c]
__device__ float g_SNt[BATCH * CHN * HW];               // norm(style)^T   [b][n][c]
__device__ float g_St [BATCH * CHN * HW];               // style^T         [b][n][c]
__device__ float g_F[BATCH * CHN * HW];                 // F* [b][n][c2]
__device__ __half g_H16[BATCH * CHN * HW];              // H' fp16 [b][c][m]
__device__ float g_O[BATCH * CHN * HW];                 // O [b][c][n]
__device__ float g_S[(size_t)BATCH * HW * HW];          // S   [b][n][m]
__device__ __half g_P16[(size_t)BATCH * HW * HW];       // softmax(S) fp16
__device__ float g_WC[2 * WSZ];                         // [Wg^T Wf | Wo Wh]
__device__ float g_w[CHN];                              // Wg^T bf
__device__ float g_bstar[CHN];                          // Wo bh + bo
__device__ float g_zero[CHN];                           // static zeros
__device__ float g_mean[2 * BATCH * CHN];
__device__ float g_rstd[2 * BATCH * CHN];

// ============================ helpers =======================================
__device__ __forceinline__ void mma_f16_f32(float* d, const uint32_t* a, const uint32_t* b) {
    asm volatile(
        "mma.sync.aligned.m16n8k16.row.col.f32.f16.f16.f32 "
        "{%0,%1,%2,%3}, {%4,%5,%6,%7}, {%8,%9}, {%0,%1,%2,%3};"
        : "+f"(d[0]), "+f"(d[1]), "+f"(d[2]), "+f"(d[3])
        : "r"(a[0]), "r"(a[1]), "r"(a[2]), "r"(a[3]), "r"(b[0]), "r"(b[1]));
}

__device__ __forceinline__ void split4(float4 v, uint32_t& h0, uint32_t& h1,
                                       uint32_t& l0, uint32_t& l1) {
    __half2 H0 = __floats2half2_rn(v.x, v.y);
    __half2 H1 = __floats2half2_rn(v.z, v.w);
    float hx = __half2float(__low2half(H0)),  hy = __half2float(__high2half(H0));
    float hz = __half2float(__low2half(H1)),  hw = __half2float(__high2half(H1));
    __half2 L0 = __floats2half2_rn(v.x - hx, v.y - hy);
    __half2 L1 = __floats2half2_rn(v.z - hz, v.w - hw);
    h0 = *(uint32_t*)&H0; h1 = *(uint32_t*)&H1;
    l0 = *(uint32_t*)&L0; l1 = *(uint32_t*)&L1;
}
__device__ __forceinline__ void split4hi(float4 v, uint32_t& h0, uint32_t& h1) {
    __half2 H0 = __floats2half2_rn(v.x, v.y);
    __half2 H1 = __floats2half2_rn(v.z, v.w);
    h0 = *(uint32_t*)&H0; h1 = *(uint32_t*)&H1;
}

// =================== fp16 split mma GEMM (NT), 512 threads ==================
// (verbatim round-11 kernel)
#define BGK_ROW   20
#define BGK_MAT   (128 * BGK_ROW)
#define BGK_STAGE (4 * BGK_MAT)
#define BGK_SMEMB (2 * BGK_STAGE * 4)            // 81920 bytes

template<int BIASMODE, bool RESID, int TERMS, bool OUTHALF>
__global__ void __launch_bounds__(512, 1)
f16_gemm_kernel(const float* __restrict__ Ag, const float* __restrict__ Bg,
                const float* __restrict__ bias, const float* __restrict__ residg,
                float* __restrict__ Cg, __half* __restrict__ Chg,
                int K, int ldA, int ldB, int ldC,
                size_t sA, size_t sB, size_t sC)
{
    extern __shared__ uint32_t smem_u32[];

    const int t    = threadIdx.x;
    const int lane = t & 31;
    const int wid  = t >> 5;
    const int wm   = wid >> 2;
    const int wn   = wid & 3;
    const int r0   = lane >> 2;
    const int c0   = lane & 3;

    const int b  = blockIdx.z;
    const int m0 = blockIdx.y * 128, n0 = blockIdx.x * 128;
    const float* A = Ag + (size_t)b * sA + (size_t)m0 * ldA;
    const float* B = Bg + (size_t)b * sB + (size_t)n0 * ldB;

    const int NC = K >> 5;
    const int lrow = t >> 2;
    const int lq4  = (t & 3) * 2;

    float4 va[2], vb[2];

    auto gload = [&](int c) {
        const int k0 = c << 5;
        #pragma unroll
        for (int j = 0; j < 2; j++) {
            va[j] = *(const float4*)&A[(size_t)lrow * ldA + k0 + (lq4 + j) * 4];
            vb[j] = *(const float4*)&B[(size_t)lrow * ldB + k0 + (lq4 + j) * 4];
        }
    };
    auto sstore = [&](int s) {
        uint32_t* base = smem_u32 + s * BGK_STAGE;
        #pragma unroll
        for (int j = 0; j < 2; j++) {
            uint32_t off = lrow * BGK_ROW + (lq4 + j) * 2;
            uint32_t h0, h1, l0, l1;
            if (TERMS == 3) {
                split4(va[j], h0, h1, l0, l1);
                base[off] = h0; base[off + 1] = h1;
                base[BGK_MAT + off] = l0; base[BGK_MAT + off + 1] = l1;
            } else {
                split4hi(va[j], h0, h1);
                base[off] = h0; base[off + 1] = h1;
            }
            split4(vb[j], h0, h1, l0, l1);
            base[2 * BGK_MAT + off] = h0; base[2 * BGK_MAT + off + 1] = h1;
            base[3 * BGK_MAT + off] = l0; base[3 * BGK_MAT + off + 1] = l1;
        }
    };

    float acc[2][4][4] = {};

    gload(0);
    sstore(0);
    if (NC > 1) gload(1);
    __syncthreads();

    for (int c = 0; c < NC; c++) {
        const int s = c & 1;
        const uint32_t* sa_h = smem_u32 + s * BGK_STAGE;
        const uint32_t* sa_l = sa_h + BGK_MAT;
        const uint32_t* sb_h = sa_h + 2 * BGK_MAT;
        const uint32_t* sb_l = sa_h + 3 * BGK_MAT;

        #pragma unroll
        for (int kk = 0; kk < 2; kk++) {
            uint32_t ah[2][4], al[2][4], bh[4][2], bl[4][2];
            const int cA = kk * 8 + c0;
            #pragma unroll
            for (int mt = 0; mt < 2; mt++) {
                int r = wm * 32 + mt * 16 + r0;
                const uint32_t* ph = &sa_h[r * BGK_ROW + cA];
                ah[mt][0] = ph[0]; ah[mt][1] = ph[8 * BGK_ROW];
                ah[mt][2] = ph[4]; ah[mt][3] = ph[8 * BGK_ROW + 4];
                if (TERMS == 3) {
                    const uint32_t* pl = &sa_l[r * BGK_ROW + cA];
                    al[mt][0] = pl[0]; al[mt][1] = pl[8 * BGK_ROW];
                    al[mt][2] = pl[4]; al[mt][3] = pl[8 * BGK_ROW + 4];
                }
            }
            #pragma unroll
            for (int nt = 0; nt < 4; nt++) {
                int n = wn * 32 + nt * 8 + r0;
                bh[nt][0] = sb_h[n * BGK_ROW + cA]; bh[nt][1] = sb_h[n * BGK_ROW + cA + 4];
                bl[nt][0] = sb_l[n * BGK_ROW + cA]; bl[nt][1] = sb_l[n * BGK_ROW + cA + 4];
            }

            if (kk == 0) { if (c + 1 < NC) sstore((c + 1) & 1); }
            else         { if (c + 2 < NC) gload(c + 2); }

            #pragma unroll
            for (int mt = 0; mt < 2; mt++)
                #pragma unroll
                for (int nt = 0; nt < 4; nt++)
                    mma_f16_f32(acc[mt][nt], ah[mt], bh[nt]);
            #pragma unroll
            for (int mt = 0; mt < 2; mt++)
                #pragma unroll
                for (int nt = 0; nt < 4; nt++)
                    mma_f16_f32(acc[mt][nt], ah[mt], bl[nt]);
            if (TERMS == 3) {
                #pragma unroll
                for (int mt = 0; mt < 2; mt++)
                    #pragma unroll
                    for (int nt = 0; nt < 4; nt++)
                        mma_f16_f32(acc[mt][nt], al[mt], bh[nt]);
            }
        }
        __syncthreads();
    }

    // ---- epilogue ----
    #pragma unroll
    for (int mt = 0; mt < 2; mt++) {
        int row = m0 + wm * 32 + mt * 16 + r0;
        float br0 = 0.f, br1 = 0.f;
        if (BIASMODE == 1) { br0 = bias[row]; br1 = bias[row + 8]; }
        #pragma unroll
        for (int nt = 0; nt < 4; nt++) {
            int col = n0 + wn * 32 + nt * 8 + c0 * 2;
            float2 v0 = make_float2(acc[mt][nt][0], acc[mt][nt][1]);
            float2 v1 = make_float2(acc[mt][nt][2], acc[mt][nt][3]);
            if (BIASMODE == 1) {
                v0.x += br0; v0.y += br0;
                v1.x += br1; v1.y += br1;
            } else if (BIASMODE == 2) {
                float bx = bias[col], by = bias[col + 1];
                v0.x += bx; v0.y += by;
                v1.x += bx; v1.y += by;
            }
            size_t o0 = (size_t)b * sC + (size_t)row * ldC + col;
            size_t o1 = (size_t)b * sC + (size_t)(row + 8) * ldC + col;
            if (OUTHALF) {
                *(__half2*)&Chg[o0] = __floats2half2_rn(v0.x, v0.y);
                *(__half2*)&Chg[o1] = __floats2half2_rn(v1.x, v1.y);
            } else {
                if (RESID) {
                    float2 rv0 = *(const float2*)&residg[o0];
                    float2 rv1 = *(const float2*)&residg[o1];
                    v0.x += rv0.x; v0.y += rv0.y;
                    v1.x += rv1.x; v1.y += rv1.y;
                }
                *(float2*)&Cg[o0] = v0;
                *(float2*)&Cg[o1] = v1;
            }
        }
    }
}

// ============ pure fp16 GEMM (NT), verbatim round-11 ========================
#define PGK_MAT   (128 * BGK_ROW)
#define PGK_STAGE (2 * PGK_MAT)
#define PGK_SMEMB (2 * PGK_STAGE * 4)            // 40960 bytes

__global__ void __launch_bounds__(512, 1)
f16_pure_gemm_kernel(const __half* __restrict__ Ag, const __half* __restrict__ Bg,
                     float* __restrict__ Cg, int K, int ldA, int ldB, int ldC,
                     size_t sA, size_t sB, size_t sC)
{
    extern __shared__ uint32_t smem_u32[];

    const int t    = threadIdx.x;
    const int lane = t & 31;
    const int wid  = t >> 5;
    const int wm   = wid >> 2;
    const int wn   = wid & 3;
    const int r0   = lane >> 2;
    const int c0   = lane & 3;

    const int b  = blockIdx.z;
    const int m0 = blockIdx.y * 128, n0 = blockIdx.x * 128;
    const __half* A = Ag + (size_t)b * sA + (size_t)m0 * ldA;
    const __half* B = Bg + (size_t)b * sB + (size_t)n0 * ldB;
    float*        C = Cg + (size_t)b * sC;

    const int NC = K >> 5;
    const int lrow = t >> 2;
    const int lq   = t & 3;

    uint4 ua, ub;
    auto gload = [&](int c) {
        const int k0 = c << 5;
        ua = *(const uint4*)&A[(size_t)lrow * ldA + k0 + lq * 8];
        ub = *(const uint4*)&B[(size_t)lrow * ldB + k0 + lq * 8];
    };
    auto sstore = [&](int s) {
        uint32_t* base = smem_u32 + s * PGK_STAGE;
        *(uint4*)&base[lrow * BGK_ROW + lq * 4] = ua;
        *(uint4*)&base[PGK_MAT + lrow * BGK_ROW + lq * 4] = ub;
    };

    float acc[2][4][4] = {};

    gload(0);
    sstore(0);
    if (NC > 1) gload(1);
    __syncthreads();

    for (int c = 0; c < NC; c++) {
        const int s = c & 1;
        const uint32_t* sa = smem_u32 + s * PGK_STAGE;
        const uint32_t* sb = sa + PGK_MAT;

        #pragma unroll
        for (int kk = 0; kk < 2; kk++) {
            uint32_t ah[2][4], bh[4][2];
            const int cA = kk * 8 + c0;
            #pragma unroll
            for (int mt = 0; mt < 2; mt++) {
                int r = wm * 32 + mt * 16 + r0;
                const uint32_t* ph = &sa[r * BGK_ROW + cA];
                ah[mt][0] = ph[0]; ah[mt][1] = ph[8 * BGK_ROW];
                ah[mt][2] = ph[4]; ah[mt][3] = ph[8 * BGK_ROW + 4];
            }
            #pragma unroll
            for (int nt = 0; nt < 4; nt++) {
                int n = wn * 32 + nt * 8 + r0;
                bh[nt][0] = sb[n * BGK_ROW + cA]; bh[nt][1] = sb[n * BGK_ROW + cA + 4];
            }

            if (kk == 0) { if (c + 1 < NC) sstore((c + 1) & 1); }
            else         { if (c + 2 < NC) gload(c + 2); }

            #pragma unroll
            for (int mt = 0; mt < 2; mt++)
                #pragma unroll
                for (int nt = 0; nt < 4; nt++)
                    mma_f16_f32(acc[mt][nt], ah[mt], bh[nt]);
        }
        __syncthreads();
    }

    #pragma unroll
    for (int mt = 0; mt < 2; mt++) {
        int row = m0 + wm * 32 + mt * 16 + r0;
        #pragma unroll
        for (int nt = 0; nt < 4; nt++) {
            int col = n0 + wn * 32 + nt * 8 + c0 * 2;
            *(float2*)&C[(size_t)row * ldC + col] =
                make_float2(acc[mt][nt][0], acc[mt][nt][1]);
            *(float2*)&C[(size_t)(row + 8) * ldC + col] =
                make_float2(acc[mt][nt][2], acc[mt][nt][3]);
        }
    }
}

// -------- WC0 = Wg^T Wf ; WC1 = Wo Wh  (simple exact fp32 SIMT GEMM) --------
__global__ void __launch_bounds__(256)
wcomb_kernel(const float* __restrict__ Wf, const float* __restrict__ Wg,
             const float* __restrict__ Wh, const float* __restrict__ Wo,
             float* __restrict__ WC)
{
    const int mode = blockIdx.z;                 // 0: Wg^T Wf, 1: Wo Wh
    const int m0 = blockIdx.y * 64, n0 = blockIdx.x * 64;
    const int t = threadIdx.x;
    const int tx = t & 15, ty = t >> 4;

    __shared__ float As[16][65], Bs[16][65];
    const float* A = (mode == 0) ? Wg : Wo;
    const float* Bsrc = (mode == 0) ? Wf : Wh;

    float acc[4][4] = {};

    for (int k0 = 0; k0 < CHN; k0 += 16) {
        #pragma unroll
        for (int i = 0; i < 4; i++) {
            int idx = t + i * 256;
            int kk = idx >> 6, mm = idx & 63;
            As[kk][mm] = (mode == 0)
                ? A[(size_t)(k0 + kk) * CHN + m0 + mm]       // Wg[k][m]
                : A[(size_t)(m0 + mm) * CHN + k0 + kk];      // Wo[m][k]
            Bs[kk][mm] = Bsrc[(size_t)(k0 + kk) * CHN + n0 + mm];  // W[k][n]
        }
        __syncthreads();
        #pragma unroll
        for (int kk = 0; kk < 16; kk++) {
            float ar[4], br[4];
            #pragma unroll
            for (int i = 0; i < 4; i++) ar[i] = As[kk][ty * 4 + i];
            #pragma unroll
            for (int j = 0; j < 4; j++) br[j] = Bs[kk][tx * 4 + j];
            #pragma unroll
            for (int i = 0; i < 4; i++)
                #pragma unroll
                for (int j = 0; j < 4; j++)
                    acc[i][j] = fmaf(ar[i], br[j], acc[i][j]);
        }
        __syncthreads();
    }

    #pragma unroll
    for (int i = 0; i < 4; i++) {
        size_t o = (size_t)mode * WSZ + (size_t)(m0 + ty * 4 + i) * CHN + n0 + tx * 4;
        float4 v = make_float4(acc[i][0], acc[i][1], acc[i][2], acc[i][3]);
        *(float4*)&WC[o] = v;
    }
}

// -------- w = Wg^T bf ; b* = Wo bh + bo -------------------------------------
__global__ void __launch_bounds__(512)
vec_kernel(const float* __restrict__ Wg, const float* __restrict__ Wo,
           const float* __restrict__ bf, const float* __restrict__ bh,
           const float* __restrict__ bo,
           float* __restrict__ w, float* __restrict__ bstar)
{
    int c = threadIdx.x;
    float s0 = 0.f, s1 = 0.f;
    for (int k = 0; k < CHN; k++) {
        s0 += Wg[(size_t)k * CHN + c] * bf[k];
        s1 += Wo[(size_t)c * CHN + k] * bh[k];
    }
    w[c] = s0;
    bstar[c] = s1 + bo[c];
}

// -------- out = O + b*[c] + content  ----------------------------------------
__global__ void __launch_bounds__(256)
finaladd_kernel(const float* __restrict__ O, const float* __restrict__ content,
                const float* __restrict__ bstar, float* __restrict__ out)
{
    size_t i = ((size_t)blockIdx.x * 256 + threadIdx.x) * 4;
    int c = (int)((i / HW) % CHN);
    float bv = bstar[c];
    float4 o = *(const float4*)&O[i];
    float4 r = *(const float4*)&content[i];
    o.x += bv + r.x; o.y += bv + r.y; o.z += bv + r.z; o.w += bv + r.w;
    *(float4*)&out[i] = o;
}

// ---------------- per-(b,c) mean / rstd over 4096 spatial elems -------------
__global__ void __launch_bounds__(256)
stats_kernel(const float* __restrict__ content, const float* __restrict__ style)
{
    int bc  = blockIdx.x;
    int sel = blockIdx.y;
    const float* x = (sel == 0 ? content : style) + (size_t)bc * HW;

    float s1 = 0.f, s2 = 0.f;
    for (int i = threadIdx.x * 4; i < HW; i += 256 * 4) {
        float4 v = *(const float4*)&x[i];
        s1 += v.x + v.y + v.z + v.w;
        s2 += v.x * v.x + v.y * v.y + v.z * v.z + v.w * v.w;
    }
    __shared__ float sh1[8], sh2[8];
    for (int o = 16; o > 0; o >>= 1) {
        s1 += __shfl_xor_sync(0xffffffffu, s1, o);
        s2 += __shfl_xor_sync(0xffffffffu, s2, o);
    }
    int warp = threadIdx.x >> 5, lane = threadIdx.x & 31;
    if (lane == 0) { sh1[warp] = s1; sh2[warp] = s2; }
    __syncthreads();
    if (threadIdx.x < 32) {
        s1 = (lane < 8) ? sh1[lane] : 0.f;
        s2 = (lane < 8) ? sh2[lane] : 0.f;
        for (int o = 4; o > 0; o >>= 1) {
            s1 += __shfl_xor_sync(0xffffffffu, s1, o);
            s2 += __shfl_xor_sync(0xffffffffu, s2, o);
        }
        if (lane == 0) {
            float mean = s1 / (float)HW;
            float var  = (s2 - s1 * mean) / (float)(HW - 1);
            int idx = sel * BATCH * CHN + bc;
            g_mean[idx] = mean;
            g_rstd[idx] = rsqrtf(var + EPSF);
        }
    }
}

// ------- transpose + normalize: [b][c][n] -> [b][n][c], 3 outputs ----------
__global__ void __launch_bounds__(256)
transnorm_kernel(const float* __restrict__ content, const float* __restrict__ style,
                 float* __restrict__ CNt, float* __restrict__ SNt,
                 float* __restrict__ St)
{
    __shared__ float tc[32][33], ts[32][33];
    int b  = blockIdx.z;
    int c0 = blockIdx.y * 32, n0 = blockIdx.x * 32;
    int t  = threadIdx.x;
    int r  = t >> 3, q = (t & 7) * 4;

    size_t ib = (size_t)b * CHN * HW + (size_t)(c0 + r) * HW + n0 + q;
    float mC = g_mean[b * CHN + c0 + r], rC = g_rstd[b * CHN + c0 + r];
    float4 v = *(const float4*)&content[ib];
    tc[r][q + 0] = (v.x - mC) * rC; tc[r][q + 1] = (v.y - mC) * rC;
    tc[r][q + 2] = (v.z - mC) * rC; tc[r][q + 3] = (v.w - mC) * rC;
    float4 w = *(const float4*)&style[ib];
    ts[r][q + 0] = w.x; ts[r][q + 1] = w.y; ts[r][q + 2] = w.z; ts[r][q + 3] = w.w;
    __syncthreads();

    size_t ob = (size_t)b * CHN * HW + (size_t)(n0 + r) * CHN + c0 + q;
    float4 o;
    o.x = tc[q + 0][r]; o.y = tc[q + 1][r]; o.z = tc[q + 2][r]; o.w = tc[q + 3][r];
    *(float4*)&CNt[ob] = o;

    float4 sraw;
    sraw.x = ts[q + 0][r]; sraw.y = ts[q + 1][r];
    sraw.z = ts[q + 2][r]; sraw.w = ts[q + 3][r];
    *(float4*)&St[ob] = sraw;

    int sidx = BATCH * CHN + b * CHN + c0 + q;
    float4 sm = *(const float4*)&g_mean[sidx];
    float4 sr = *(const float4*)&g_rstd[sidx];
    float4 sn;
    sn.x = (sraw.x - sm.x) * sr.x; sn.y = (sraw.y - sm.y) * sr.y;
    sn.z = (sraw.z - sm.z) * sr.z; sn.w = (sraw.w - sm.w) * sr.w;
    *(float4*)&SNt[ob] = sn;
}

// ------- row softmax over 4096, fp16 output ---------------------------------
__global__ void __launch_bounds__(256)
softmax_kernel(const float* __restrict__ S, __half* __restrict__ P16)
{
    __shared__ float buf[HW];
    __shared__ float red1[8], red2[8];
    const float* p = S + (size_t)blockIdx.x * HW;
    __half* po = P16 + (size_t)blockIdx.x * HW;
    int t = threadIdx.x, lane = t & 31, warp = t >> 5;

    float m = -3.4e38f;
    for (int i = t * 4; i < HW; i += 1024) {
        float4 v = *(const float4*)&p[i];
        *(float4*)&buf[i] = v;
        m = fmaxf(m, fmaxf(fmaxf(v.x, v.y), fmaxf(v.z, v.w)));
    }
    for (int o = 16; o > 0; o >>= 1) m = fmaxf(m, __shfl_xor_sync(0xffffffffu, m, o));
    if (lane == 0) red1[warp] = m;
    __syncthreads();
    if (t < 32) {
        m = (lane < 8) ? red1[lane] : -3.4e38f;
        for (int o = 4; o > 0; o >>= 1) m = fmaxf(m, __shfl_xor_sync(0xffffffffu, m, o));
        if (lane == 0) red1[0] = m;
    }
    __syncthreads();
    m = red1[0];

    float s = 0.f;
    for (int i = t * 4; i < HW; i += 1024) {
        float4 v = *(const float4*)&buf[i];
        v.x = __expf(v.x - m); v.y = __expf(v.y - m);
        v.z = __expf(v.z - m); v.w = __expf(v.w - m);
        *(float4*)&buf[i] = v;
        s += v.x + v.y + v.z + v.w;
    }
    for (int o = 16; o > 0; o >>= 1) s += __shfl_xor_sync(0xffffffffu, s, o);
    if (lane == 0) red2[warp] = s;
    __syncthreads();
    if (t < 32) {
        s = (lane < 8) ? red2[lane] : 0.f;
        for (int o = 4; o > 0; o >>= 1) s += __shfl_xor_sync(0xffffffffu, s, o);
        if (lane == 0) red2[0] = s;
    }
    __syncthreads();
    float inv = 1.0f / red2[0];
    for (int i = t * 4; i < HW; i += 1024) {
        float4 v = *(const float4*)&buf[i];
        *(__half2*)&po[i]     = __floats2half2_rn(v.x * inv, v.y * inv);
        *(__half2*)&po[i + 2] = __floats2half2_rn(v.z * inv, v.w * inv);
    }
}

// ---------------- launch --------------------------------------------------
extern "C" void kernel_launch(void* const* d_in, const int* in_sizes, int n_in,
                              void* d_out, int out_size)
{
    const float* content = (const float*)d_in[0];
    const float* style   = (const float*)d_in[1];
    const float* Wf = (const float*)d_in[2]; const float* bf = (const float*)d_in[3];
    const float* Wg = (const float*)d_in[4]; const float* bg = (const float*)d_in[5];
    const float* Wh = (const float*)d_in[6]; const float* bh = (const float*)d_in[7];
    const float* Wo = (const float*)d_in[8]; const float* bo = (const float*)d_in[9];
    float* out = (float*)d_out;
    (void)bg;   // cancels under softmax shift-invariance

    float *pCNt, *pSNt, *pSt, *pF, *pO, *pS, *pWC, *pw, *pbs, *pzero;
    __half *pH16, *pP16;
    cudaGetSymbolAddress((void**)&pCNt, g_CNt);
    cudaGetSymbolAddress((void**)&pSNt, g_SNt);
    cudaGetSymbolAddress((void**)&pSt,  g_St);
    cudaGetSymbolAddress((void**)&pF,   g_F);
    cudaGetSymbolAddress((void**)&pH16, g_H16);
    cudaGetSymbolAddress((void**)&pO,   g_O);
    cudaGetSymbolAddress((void**)&pS,   g_S);
    cudaGetSymbolAddress((void**)&pP16, g_P16);
    cudaGetSymbolAddress((void**)&pWC,  g_WC);
    cudaGetSymbolAddress((void**)&pw,   g_w);
    cudaGetSymbolAddress((void**)&pbs,  g_bstar);
    cudaGetSymbolAddress((void**)&pzero, g_zero);

    cudaFuncSetAttribute(f16_gemm_kernel<2, false, 3, false>,
                         cudaFuncAttributeMaxDynamicSharedMemorySize, BGK_SMEMB);
    cudaFuncSetAttribute(f16_gemm_kernel<1, false, 2, true>,
                         cudaFuncAttributeMaxDynamicSharedMemorySize, BGK_SMEMB);
    cudaFuncSetAttribute(f16_gemm_kernel<0, false, 3, false>,
                         cudaFuncAttributeMaxDynamicSharedMemorySize, BGK_SMEMB);
    cudaFuncSetAttribute(f16_pure_gemm_kernel,
                         cudaFuncAttributeMaxDynamicSharedMemorySize, PGK_SMEMB);

    const size_t sBCHW = (size_t)CHN * HW;
    const size_t sBHH  = (size_t)HW * HW;

    // 1) stats + combined weights + vectors
    stats_kernel<<<dim3(BATCH * CHN, 2), 256>>>(content, style);
    wcomb_kernel<<<dim3(8, 8, 2), 256>>>(Wf, Wg, Wh, Wo, pWC);
    vec_kernel<<<1, 512>>>(Wg, Wo, bf, bh, bo, pw, pbs);

    // 2) transpose + normalize
    transnorm_kernel<<<dim3(HW / 32, CHN / 32, BATCH), 256>>>(
        content, style, pCNt, pSNt, pSt);

    // 3) F*[n,c2] = CN_t[n,:] . WC0[c2,:] + w[c2]   (3 terms)
    f16_gemm_kernel<2, false, 3, false><<<dim3(CHN / 128, HW / 128, BATCH), 512, BGK_SMEMB>>>(
        pCNt, pWC, pw, nullptr, pF, nullptr, CHN, CHN, CHN, CHN, sBCHW, 0, sBCHW);

    // 4) H'[c,m] = WC1[c,:] . St[m,:]   (2 terms; zero bias; fp16 out)
    f16_gemm_kernel<1, false, 2, true><<<dim3(HW / 128, CHN / 128, BATCH), 512, BGK_SMEMB>>>(
        pWC + WSZ, pSt, pzero, nullptr, nullptr, pH16,
        CHN, CHN, CHN, HW, 0, sBCHW, sBCHW);

    // 5) S[n,m] = F*[n,:] . SN_t[m,:]   (3 terms; logits)
    f16_gemm_kernel<0, false, 3, false><<<dim3(HW / 128, HW / 128, BATCH), 512, BGK_SMEMB>>>(
        pF, pSNt, nullptr, nullptr, pS, nullptr, CHN, CHN, CHN, HW,
        sBCHW, sBCHW, sBHH);

    // 6) softmax rows of S -> fp16 P
    softmax_kernel<<<BATCH * HW, 256>>>(pS, pP16);

    // 7) O[c,n] = H'[c,:] . P[n,:]   (pure fp16)
    f16_pure_gemm_kernel<<<dim3(HW / 128, CHN / 128, BATCH), 512, PGK_SMEMB>>>(
        pH16, pP16, pO, HW, HW, HW, HW, sBCHW, sBHH, sBCHW);

    // 8) out = O + b*[c] + content
    finaladd_kernel<<<(int)(BATCH * sBCHW / 1024), 256>>>(pO, content, pbs, out);
}

// round 16
// speedup vs baseline: 1.9860x; 1.0824x over previous
#include <cuda_runtime.h>
#include <cuda_fp16.h>
#include <cstdint>
#include <math.h>

#define BATCH 4
#define CHN   512
#define HW    4096
#define EPSF  1e-5f
#define WSZ   (CHN * CHN)

// ---------------- scratch (device globals; no allocations allowed) ----------
__device__ float g_CNt[BATCH * CHN * HW];               // norm(content)^T [b][n][c]
__device__ float g_SNt[BATCH * CHN * HW];               // norm(style)^T   [b][n][c]
__device__ float g_St [BATCH * CHN * HW];               // style^T         [b][n][c]
__device__ float g_F[BATCH * CHN * HW];                 // F* [b][n][c2]
__device__ __half g_H16[BATCH * CHN * HW];              // H' fp16 [b][c][m]
__device__ float g_O[BATCH * CHN * HW];                 // O [b][c][n]
__device__ float g_S[(size_t)BATCH * HW * HW];          // S   [b][n][m]
__device__ __half g_P16[(size_t)BATCH * HW * HW];       // softmax(S) fp16
__device__ float g_WC[2 * WSZ];                         // [Wg^T Wf | Wo Wh]
__device__ float g_w[CHN];                              // Wg^T bf
__device__ float g_bstar[CHN];                          // Wo bh + bo
__device__ float g_zero[CHN];                           // static zeros
__device__ float g_mean[2 * BATCH * CHN];
__device__ float g_rstd[2 * BATCH * CHN];

// ============================ helpers =======================================
__device__ __forceinline__ void mma_f16_f32(float* d, const uint32_t* a, const uint32_t* b) {
    asm volatile(
        "mma.sync.aligned.m16n8k16.row.col.f32.f16.f16.f32 "
        "{%0,%1,%2,%3}, {%4,%5,%6,%7}, {%8,%9}, {%0,%1,%2,%3};"
        : "+f"(d[0]), "+f"(d[1]), "+f"(d[2]), "+f"(d[3])
        : "r"(a[0]), "r"(a[1]), "r"(a[2]), "r"(a[3]), "r"(b[0]), "r"(b[1]));
}

__device__ __forceinline__ void split4(float4 v, uint32_t& h0, uint32_t& h1,
                                       uint32_t& l0, uint32_t& l1) {
    __half2 H0 = __floats2half2_rn(v.x, v.y);
    __half2 H1 = __floats2half2_rn(v.z, v.w);
    float hx = __half2float(__low2half(H0)),  hy = __half2float(__high2half(H0));
    float hz = __half2float(__low2half(H1)),  hw = __half2float(__high2half(H1));
    __half2 L0 = __floats2half2_rn(v.x - hx, v.y - hy);
    __half2 L1 = __floats2half2_rn(v.z - hz, v.w - hw);
    h0 = *(uint32_t*)&H0; h1 = *(uint32_t*)&H1;
    l0 = *(uint32_t*)&L0; l1 = *(uint32_t*)&L1;
}
__device__ __forceinline__ void split4hi(float4 v, uint32_t& h0, uint32_t& h1) {
    __half2 H0 = __floats2half2_rn(v.x, v.y);
    __half2 H1 = __floats2half2_rn(v.z, v.w);
    h0 = *(uint32_t*)&H0; h1 = *(uint32_t*)&H1;
}

// fast exp on the FMA pipe: e^x = 2^(x*log2e), valid for x <= 0
__device__ __forceinline__ float fexp(float x) {
    float t = x * 1.44269504f;
    int n = __float2int_rd(t);
    float f = t - (float)n;
    float p = 1.0f + f * (0.69314718f + f * (0.24022651f + f * (0.05550411f
              + f * (0.00961813f + f * (0.00133336f + f * 0.00015404f)))));
    n = max(n, -127);
    return __int_as_float((uint32_t)(n + 127) << 23) * p;
}

// =================== fp16 split mma GEMM (NT), 512 threads ==================
// (verbatim round-11/14 kernel)
#define BGK_ROW   20
#define BGK_MAT   (128 * BGK_ROW)
#define BGK_STAGE (4 * BGK_MAT)
#define BGK_SMEMB (2 * BGK_STAGE * 4)            // 81920 bytes

template<int BIASMODE, bool RESID, int TERMS, bool OUTHALF>
__global__ void __launch_bounds__(512, 1)
f16_gemm_kernel(const float* __restrict__ Ag, const float* __restrict__ Bg,
                const float* __restrict__ bias, const float* __restrict__ residg,
                float* __restrict__ Cg, __half* __restrict__ Chg,
                int K, int ldA, int ldB, int ldC,
                size_t sA, size_t sB, size_t sC)
{
    extern __shared__ uint32_t smem_u32[];

    const int t    = threadIdx.x;
    const int lane = t & 31;
    const int wid  = t >> 5;
    const int wm   = wid >> 2;
    const int wn   = wid & 3;
    const int r0   = lane >> 2;
    const int c0   = lane & 3;

    const int b  = blockIdx.z;
    const int m0 = blockIdx.y * 128, n0 = blockIdx.x * 128;
    const float* A = Ag + (size_t)b * sA + (size_t)m0 * ldA;
    const float* B = Bg + (size_t)b * sB + (size_t)n0 * ldB;

    const int NC = K >> 5;
    const int lrow = t >> 2;
    const int lq4  = (t & 3) * 2;

    float4 va[2], vb[2];

    auto gload = [&](int c) {
        const int k0 = c << 5;
        #pragma unroll
        for (int j = 0; j < 2; j++) {
            va[j] = *(const float4*)&A[(size_t)lrow * ldA + k0 + (lq4 + j) * 4];
            vb[j] = *(const float4*)&B[(size_t)lrow * ldB + k0 + (lq4 + j) * 4];
        }
    };
    auto sstore = [&](int s) {
        uint32_t* base = smem_u32 + s * BGK_STAGE;
        #pragma unroll
        for (int j = 0; j < 2; j++) {
            uint32_t off = lrow * BGK_ROW + (lq4 + j) * 2;
            uint32_t h0, h1, l0, l1;
            if (TERMS == 3) {
                split4(va[j], h0, h1, l0, l1);
                base[off] = h0; base[off + 1] = h1;
                base[BGK_MAT + off] = l0; base[BGK_MAT + off + 1] = l1;
            } else {
                split4hi(va[j], h0, h1);
                base[off] = h0; base[off + 1] = h1;
            }
            split4(vb[j], h0, h1, l0, l1);
            base[2 * BGK_MAT + off] = h0; base[2 * BGK_MAT + off + 1] = h1;
            base[3 * BGK_MAT + off] = l0; base[3 * BGK_MAT + off + 1] = l1;
        }
    };

    float acc[2][4][4] = {};

    gload(0);
    sstore(0);
    if (NC > 1) gload(1);
    __syncthreads();

    for (int c = 0; c < NC; c++) {
        const int s = c & 1;
        const uint32_t* sa_h = smem_u32 + s * BGK_STAGE;
        const uint32_t* sa_l = sa_h + BGK_MAT;
        const uint32_t* sb_h = sa_h + 2 * BGK_MAT;
        const uint32_t* sb_l = sa_h + 3 * BGK_MAT;

        #pragma unroll
        for (int kk = 0; kk < 2; kk++) {
            uint32_t ah[2][4], al[2][4], bh[4][2], bl[4][2];
            const int cA = kk * 8 + c0;
            #pragma unroll
            for (int mt = 0; mt < 2; mt++) {
                int r = wm * 32 + mt * 16 + r0;
                const uint32_t* ph = &sa_h[r * BGK_ROW + cA];
                ah[mt][0] = ph[0]; ah[mt][1] = ph[8 * BGK_ROW];
                ah[mt][2] = ph[4]; ah[mt][3] = ph[8 * BGK_ROW + 4];
                if (TERMS == 3) {
                    const uint32_t* pl = &sa_l[r * BGK_ROW + cA];
                    al[mt][0] = pl[0]; al[mt][1] = pl[8 * BGK_ROW];
                    al[mt][2] = pl[4]; al[mt][3] = pl[8 * BGK_ROW + 4];
                }
            }
            #pragma unroll
            for (int nt = 0; nt < 4; nt++) {
                int n = wn * 32 + nt * 8 + r0;
                bh[nt][0] = sb_h[n * BGK_ROW + cA]; bh[nt][1] = sb_h[n * BGK_ROW + cA + 4];
                bl[nt][0] = sb_l[n * BGK_ROW + cA]; bl[nt][1] = sb_l[n * BGK_ROW + cA + 4];
            }

            if (kk == 0) { if (c + 1 < NC) sstore((c + 1) & 1); }
            else         { if (c + 2 < NC) gload(c + 2); }

            #pragma unroll
            for (int mt = 0; mt < 2; mt++)
                #pragma unroll
                for (int nt = 0; nt < 4; nt++)
                    mma_f16_f32(acc[mt][nt], ah[mt], bh[nt]);
            #pragma unroll
            for (int mt = 0; mt < 2; mt++)
                #pragma unroll
                for (int nt = 0; nt < 4; nt++)
                    mma_f16_f32(acc[mt][nt], ah[mt], bl[nt]);
            if (TERMS == 3) {
                #pragma unroll
                for (int mt = 0; mt < 2; mt++)
                    #pragma unroll
                    for (int nt = 0; nt < 4; nt++)
                        mma_f16_f32(acc[mt][nt], al[mt], bh[nt]);
            }
        }
        __syncthreads();
    }

    // ---- epilogue ----
    #pragma unroll
    for (int mt = 0; mt < 2; mt++) {
        int row = m0 + wm * 32 + mt * 16 + r0;
        float br0 = 0.f, br1 = 0.f;
        if (BIASMODE == 1) { br0 = bias[row]; br1 = bias[row + 8]; }
        #pragma unroll
        for (int nt = 0; nt < 4; nt++) {
            int col = n0 + wn * 32 + nt * 8 + c0 * 2;
            float2 v0 = make_float2(acc[mt][nt][0], acc[mt][nt][1]);
            float2 v1 = make_float2(acc[mt][nt][2], acc[mt][nt][3]);
            if (BIASMODE == 1) {
                v0.x += br0; v0.y += br0;
                v1.x += br1; v1.y += br1;
            } else if (BIASMODE == 2) {
                float bx = bias[col], by = bias[col + 1];
                v0.x += bx; v0.y += by;
                v1.x += bx; v1.y += by;
            }
            size_t o0 = (size_t)b * sC + (size_t)row * ldC + col;
            size_t o1 = (size_t)b * sC + (size_t)(row + 8) * ldC + col;
            if (OUTHALF) {
                *(__half2*)&Chg[o0] = __floats2half2_rn(v0.x, v0.y);
                *(__half2*)&Chg[o1] = __floats2half2_rn(v1.x, v1.y);
            } else {
                if (RESID) {
                    float2 rv0 = *(const float2*)&residg[o0];
                    float2 rv1 = *(const float2*)&residg[o1];
                    v0.x += rv0.x; v0.y += rv0.y;
                    v1.x += rv1.x; v1.y += rv1.y;
                }
                *(float2*)&Cg[o0] = v0;
                *(float2*)&Cg[o1] = v1;
            }
        }
    }
}

// ============ pure fp16 GEMM (NT), verbatim round-14 ========================
#define PGK_MAT   (128 * BGK_ROW)
#define PGK_STAGE (2 * PGK_MAT)
#define PGK_SMEMB (2 * PGK_STAGE * 4)            // 40960 bytes

__global__ void __launch_bounds__(512, 1)
f16_pure_gemm_kernel(const __half* __restrict__ Ag, const __half* __restrict__ Bg,
                     float* __restrict__ Cg, int K, int ldA, int ldB, int ldC,
                     size_t sA, size_t sB, size_t sC)
{
    extern __shared__ uint32_t smem_u32[];

    const int t    = threadIdx.x;
    const int lane = t & 31;
    const int wid  = t >> 5;
    const int wm   = wid >> 2;
    const int wn   = wid & 3;
    const int r0   = lane >> 2;
    const int c0   = lane & 3;

    const int b  = blockIdx.z;
    const int m0 = blockIdx.y * 128, n0 = blockIdx.x * 128;
    const __half* A = Ag + (size_t)b * sA + (size_t)m0 * ldA;
    const __half* B = Bg + (size_t)b * sB + (size_t)n0 * ldB;
    float*        C = Cg + (size_t)b * sC;

    const int NC = K >> 5;
    const int lrow = t >> 2;
    const int lq   = t & 3;

    uint4 ua, ub;
    auto gload = [&](int c) {
        const int k0 = c << 5;
        ua = *(const uint4*)&A[(size_t)lrow * ldA + k0 + lq * 8];
        ub = *(const uint4*)&B[(size_t)lrow * ldB + k0 + lq * 8];
    };
    auto sstore = [&](int s) {
        uint32_t* base = smem_u32 + s * PGK_STAGE;
        *(uint4*)&base[lrow * BGK_ROW + lq * 4] = ua;
        *(uint4*)&base[PGK_MAT + lrow * BGK_ROW + lq * 4] = ub;
    };

    float acc[2][4][4] = {};

    gload(0);
    sstore(0);
    if (NC > 1) gload(1);
    __syncthreads();

    for (int c = 0; c < NC; c++) {
        const int s = c & 1;
        const uint32_t* sa = smem_u32 + s * PGK_STAGE;
        const uint32_t* sb = sa + PGK_MAT;

        #pragma unroll
        for (int kk = 0; kk < 2; kk++) {
            uint32_t ah[2][4], bh[4][2];
            const int cA = kk * 8 + c0;
            #pragma unroll
            for (int mt = 0; mt < 2; mt++) {
                int r = wm * 32 + mt * 16 + r0;
                const uint32_t* ph = &sa[r * BGK_ROW + cA];
                ah[mt][0] = ph[0]; ah[mt][1] = ph[8 * BGK_ROW];
                ah[mt][2] = ph[4]; ah[mt][3] = ph[8 * BGK_ROW + 4];
            }
            #pragma unroll
            for (int nt = 0; nt < 4; nt++) {
                int n = wn * 32 + nt * 8 + r0;
                bh[nt][0] = sb[n * BGK_ROW + cA]; bh[nt][1] = sb[n * BGK_ROW + cA + 4];
            }

            if (kk == 0) { if (c + 1 < NC) sstore((c + 1) & 1); }
            else         { if (c + 2 < NC) gload(c + 2); }

            #pragma unroll
            for (int mt = 0; mt < 2; mt++)
                #pragma unroll
                for (int nt = 0; nt < 4; nt++)
                    mma_f16_f32(acc[mt][nt], ah[mt], bh[nt]);
        }
        __syncthreads();
    }

    #pragma unroll
    for (int mt = 0; mt < 2; mt++) {
        int row = m0 + wm * 32 + mt * 16 + r0;
        #pragma unroll
        for (int nt = 0; nt < 4; nt++) {
            int col = n0 + wn * 32 + nt * 8 + c0 * 2;
            *(float2*)&C[(size_t)row * ldC + col] =
                make_float2(acc[mt][nt][0], acc[mt][nt][1]);
            *(float2*)&C[(size_t)(row + 8) * ldC + col] =
                make_float2(acc[mt][nt][2], acc[mt][nt][3]);
        }
    }
}

// -------- WC0 = Wg^T Wf ; WC1 = Wo Wh  (simple exact fp32 SIMT GEMM) --------
__global__ void __launch_bounds__(256)
wcomb_kernel(const float* __restrict__ Wf, const float* __restrict__ Wg,
             const float* __restrict__ Wh, const float* __restrict__ Wo,
             float* __restrict__ WC)
{
    const int mode = blockIdx.z;                 // 0: Wg^T Wf, 1: Wo Wh
    const int m0 = blockIdx.y * 64, n0 = blockIdx.x * 64;
    const int t = threadIdx.x;
    const int tx = t & 15, ty = t >> 4;

    __shared__ float As[16][65], Bs[16][65];
    const float* A = (mode == 0) ? Wg : Wo;
    const float* Bsrc = (mode == 0) ? Wf : Wh;

    float acc[4][4] = {};

    for (int k0 = 0; k0 < CHN; k0 += 16) {
        #pragma unroll
        for (int i = 0; i < 4; i++) {
            int idx = t + i * 256;
            int kk = idx >> 6, mm = idx & 63;
            As[kk][mm] = (mode == 0)
                ? A[(size_t)(k0 + kk) * CHN + m0 + mm]
                : A[(size_t)(m0 + mm) * CHN + k0 + kk];
            Bs[kk][mm] = Bsrc[(size_t)(k0 + kk) * CHN + n0 + mm];
        }
        __syncthreads();
        #pragma unroll
        for (int kk = 0; kk < 16; kk++) {
            float ar[4], br[4];
            #pragma unroll
            for (int i = 0; i < 4; i++) ar[i] = As[kk][ty * 4 + i];
            #pragma unroll
            for (int j = 0; j < 4; j++) br[j] = Bs[kk][tx * 4 + j];
            #pragma unroll
            for (int i = 0; i < 4; i++)
                #pragma unroll
                for (int j = 0; j < 4; j++)
                    acc[i][j] = fmaf(ar[i], br[j], acc[i][j]);
        }
        __syncthreads();
    }

    #pragma unroll
    for (int i = 0; i < 4; i++) {
        size_t o = (size_t)mode * WSZ + (size_t)(m0 + ty * 4 + i) * CHN + n0 + tx * 4;
        *(float4*)&WC[o] = make_float4(acc[i][0], acc[i][1], acc[i][2], acc[i][3]);
    }
}

// -------- w = Wg^T bf ; b* = Wo bh + bo  (parallelized) ---------------------
__global__ void __launch_bounds__(64)
vec_kernel(const float* __restrict__ Wg, const float* __restrict__ Wo,
           const float* __restrict__ bf, const float* __restrict__ bh,
           const float* __restrict__ bo,
           float* __restrict__ w, float* __restrict__ bstar)
{
    int c = blockIdx.x * 64 + threadIdx.x;
    if (blockIdx.y == 0) {
        float s = 0.f;
        for (int k = 0; k < CHN; k++) s += Wg[(size_t)k * CHN + c] * bf[k];
        w[c] = s;
    } else {
        float s = 0.f;
        for (int k = 0; k < CHN; k++) s += Wo[(size_t)c * CHN + k] * bh[k];
        bstar[c] = s + bo[c];
    }
}

// -------- out = O + b*[c] + content  ----------------------------------------
__global__ void __launch_bounds__(256)
finaladd_kernel(const float* __restrict__ O, const float* __restrict__ content,
                const float* __restrict__ bstar, float* __restrict__ out)
{
    size_t i = ((size_t)blockIdx.x * 256 + threadIdx.x) * 4;
    int c = (int)((i / HW) % CHN);
    float bv = bstar[c];
    float4 o = *(const float4*)&O[i];
    float4 r = *(const float4*)&content[i];
    o.x += bv + r.x; o.y += bv + r.y; o.z += bv + r.z; o.w += bv + r.w;
    *(float4*)&out[i] = o;
}

// ---------------- per-(b,c) mean / rstd over 4096 spatial elems -------------
__global__ void __launch_bounds__(256)
stats_kernel(const float* __restrict__ content, const float* __restrict__ style)
{
    int bc  = blockIdx.x;
    int sel = blockIdx.y;
    const float* x = (sel == 0 ? content : style) + (size_t)bc * HW;

    float s1 = 0.f, s2 = 0.f;
    for (int i = threadIdx.x * 4; i < HW; i += 256 * 4) {
        float4 v = *(const float4*)&x[i];
        s1 += v.x + v.y + v.z + v.w;
        s2 += v.x * v.x + v.y * v.y + v.z * v.z + v.w * v.w;
    }
    __shared__ float sh1[8], sh2[8];
    for (int o = 16; o > 0; o >>= 1) {
        s1 += __shfl_xor_sync(0xffffffffu, s1, o);
        s2 += __shfl_xor_sync(0xffffffffu, s2, o);
    }
    int warp = threadIdx.x >> 5, lane = threadIdx.x & 31;
    if (lane == 0) { sh1[warp] = s1; sh2[warp] = s2; }
    __syncthreads();
    if (threadIdx.x < 32) {
        s1 = (lane < 8) ? sh1[lane] : 0.f;
        s2 = (lane < 8) ? sh2[lane] : 0.f;
        for (int o = 4; o > 0; o >>= 1) {
            s1 += __shfl_xor_sync(0xffffffffu, s1, o);
            s2 += __shfl_xor_sync(0xffffffffu, s2, o);
        }
        if (lane == 0) {
            float mean = s1 / (float)HW;
            float var  = (s2 - s1 * mean) / (float)(HW - 1);
            int idx = sel * BATCH * CHN + bc;
            g_mean[idx] = mean;
            g_rstd[idx] = rsqrtf(var + EPSF);
        }
    }
}

// ------- transpose + normalize: [b][c][n] -> [b][n][c], 3 outputs ----------
__global__ void __launch_bounds__(256)
transnorm_kernel(const float* __restrict__ content, const float* __restrict__ style,
                 float* __restrict__ CNt, float* __restrict__ SNt,
                 float* __restrict__ St)
{
    __shared__ float tc[32][33], ts[32][33];
    int b  = blockIdx.z;
    int c0 = blockIdx.y * 32, n0 = blockIdx.x * 32;
    int t  = threadIdx.x;
    int r  = t >> 3, q = (t & 7) * 4;

    size_t ib = (size_t)b * CHN * HW + (size_t)(c0 + r) * HW + n0 + q;
    float mC = g_mean[b * CHN + c0 + r], rC = g_rstd[b * CHN + c0 + r];
    float4 v = *(const float4*)&content[ib];
    tc[r][q + 0] = (v.x - mC) * rC; tc[r][q + 1] = (v.y - mC) * rC;
    tc[r][q + 2] = (v.z - mC) * rC; tc[r][q + 3] = (v.w - mC) * rC;
    float4 w = *(const float4*)&style[ib];
    ts[r][q + 0] = w.x; ts[r][q + 1] = w.y; ts[r][q + 2] = w.z; ts[r][q + 3] = w.w;
    __syncthreads();

    size_t ob = (size_t)b * CHN * HW + (size_t)(n0 + r) * CHN + c0 + q;
    float4 o;
    o.x = tc[q + 0][r]; o.y = tc[q + 1][r]; o.z = tc[q + 2][r]; o.w = tc[q + 3][r];
    *(float4*)&CNt[ob] = o;

    float4 sraw;
    sraw.x = ts[q + 0][r]; sraw.y = ts[q + 1][r];
    sraw.z = ts[q + 2][r]; sraw.w = ts[q + 3][r];
    *(float4*)&St[ob] = sraw;

    int sidx = BATCH * CHN + b * CHN + c0 + q;
    float4 sm = *(const float4*)&g_mean[sidx];
    float4 sr = *(const float4*)&g_rstd[sidx];
    float4 sn;
    sn.x = (sraw.x - sm.x) * sr.x; sn.y = (sraw.y - sm.y) * sr.y;
    sn.z = (sraw.z - sm.z) * sr.z; sn.w = (sraw.w - sm.w) * sr.w;
    *(float4*)&SNt[ob] = sn;
}

// ------- row softmax over 4096, fp16 output, FMA-pipe exp -------------------
__global__ void __launch_bounds__(256)
softmax_kernel(const float* __restrict__ S, __half* __restrict__ P16)
{
    __shared__ float buf[HW];
    __shared__ float red1[8], red2[8];
    const float* p = S + (size_t)blockIdx.x * HW;
    __half* po = P16 + (size_t)blockIdx.x * HW;
    int t = threadIdx.x, lane = t & 31, warp = t >> 5;

    float m = -3.4e38f;
    for (int i = t * 4; i < HW; i += 1024) {
        float4 v = *(const float4*)&p[i];
        *(float4*)&buf[i] = v;
        m = fmaxf(m, fmaxf(fmaxf(v.x, v.y), fmaxf(v.z, v.w)));
    }
    for (int o = 16; o > 0; o >>= 1) m = fmaxf(m, __shfl_xor_sync(0xffffffffu, m, o));
    if (lane == 0) red1[warp] = m;
    __syncthreads();
    if (t < 32) {
        m = (lane < 8) ? red1[lane] : -3.4e38f;
        for (int o = 4; o > 0; o >>= 1) m = fmaxf(m, __shfl_xor_sync(0xffffffffu, m, o));
        if (lane == 0) red1[0] = m;
    }
    __syncthreads();
    m = red1[0];

    float s = 0.f;
    for (int i = t * 4; i < HW; i += 1024) {
        float4 v = *(const float4*)&buf[i];
        v.x = fexp(v.x - m); v.y = fexp(v.y - m);
        v.z = fexp(v.z - m); v.w = fexp(v.w - m);
        *(float4*)&buf[i] = v;
        s += v.x + v.y + v.z + v.w;
    }
    for (int o = 16; o > 0; o >>= 1) s += __shfl_xor_sync(0xffffffffu, s, o);
    if (lane == 0) red2[warp] = s;
    __syncthreads();
    if (t < 32) {
        s = (lane < 8) ? red2[lane] : 0.f;
        for (int o = 4; o > 0; o >>= 1) s += __shfl_xor_sync(0xffffffffu, s, o);
        if (lane == 0) red2[0] = s;
    }
    __syncthreads();
    float inv = 1.0f / red2[0];
    for (int i = t * 4; i < HW; i += 1024) {
        float4 v = *(const float4*)&buf[i];
        *(__half2*)&po[i]     = __floats2half2_rn(v.x * inv, v.y * inv);
        *(__half2*)&po[i + 2] = __floats2half2_rn(v.z * inv, v.w * inv);
    }
}

// ---------------- launch --------------------------------------------------
extern "C" void kernel_launch(void* const* d_in, const int* in_sizes, int n_in,
                              void* d_out, int out_size)
{
    const float* content = (const float*)d_in[0];
    const float* style   = (const float*)d_in[1];
    const float* Wf = (const float*)d_in[2]; const float* bf = (const float*)d_in[3];
    const float* Wg = (const float*)d_in[4]; const float* bg = (const float*)d_in[5];
    const float* Wh = (const float*)d_in[6]; const float* bh = (const float*)d_in[7];
    const float* Wo = (const float*)d_in[8]; const float* bo = (const float*)d_in[9];
    float* out = (float*)d_out;
    (void)bg;   // cancels under softmax shift-invariance

    float *pCNt, *pSNt, *pSt, *pF, *pO, *pS, *pWC, *pw, *pbs, *pzero;
    __half *pH16, *pP16;
    cudaGetSymbolAddress((void**)&pCNt, g_CNt);
    cudaGetSymbolAddress((void**)&pSNt, g_SNt);
    cudaGetSymbolAddress((void**)&pSt,  g_St);
    cudaGetSymbolAddress((void**)&pF,   g_F);
    cudaGetSymbolAddress((void**)&pH16, g_H16);
    cudaGetSymbolAddress((void**)&pO,   g_O);
    cudaGetSymbolAddress((void**)&pS,   g_S);
    cudaGetSymbolAddress((void**)&pP16, g_P16);
    cudaGetSymbolAddress((void**)&pWC,  g_WC);
    cudaGetSymbolAddress((void**)&pw,   g_w);
    cudaGetSymbolAddress((void**)&pbs,  g_bstar);
    cudaGetSymbolAddress((void**)&pzero, g_zero);

    cudaFuncSetAttribute(f16_gemm_kernel<2, false, 3, false>,
                         cudaFuncAttributeMaxDynamicSharedMemorySize, BGK_SMEMB);
    cudaFuncSetAttribute(f16_gemm_kernel<1, false, 2, true>,
                         cudaFuncAttributeMaxDynamicSharedMemorySize, BGK_SMEMB);
    cudaFuncSetAttribute(f16_gemm_kernel<0, false, 3, false>,
                         cudaFuncAttributeMaxDynamicSharedMemorySize, BGK_SMEMB);
    cudaFuncSetAttribute(f16_pure_gemm_kernel,
                         cudaFuncAttributeMaxDynamicSharedMemorySize, PGK_SMEMB);

    const size_t sBCHW = (size_t)CHN * HW;
    const size_t sBHH  = (size_t)HW * HW;

    // 1) stats + combined weights + vectors
    stats_kernel<<<dim3(BATCH * CHN, 2), 256>>>(content, style);
    wcomb_kernel<<<dim3(8, 8, 2), 256>>>(Wf, Wg, Wh, Wo, pWC);
    vec_kernel<<<dim3(8, 2), 64>>>(Wg, Wo, bf, bh, bo, pw, pbs);

    // 2) transpose + normalize
    transnorm_kernel<<<dim3(HW / 32, CHN / 32, BATCH), 256>>>(
        content, style, pCNt, pSNt, pSt);

    // 3) F*[n,c2] = CN_t[n,:] . WC0[c2,:] + w[c2]   (3 terms)
    f16_gemm_kernel<2, false, 3, false><<<dim3(CHN / 128, HW / 128, BATCH), 512, BGK_SMEMB>>>(
        pCNt, pWC, pw, nullptr, pF, nullptr, CHN, CHN, CHN, CHN, sBCHW, 0, sBCHW);

    // 4) H'[c,m] = WC1[c,:] . St[m,:]   (2 terms; zero bias; fp16 out)
    f16_gemm_kernel<1, false, 2, true><<<dim3(HW / 128, CHN / 128, BATCH), 512, BGK_SMEMB>>>(
        pWC + WSZ, pSt, pzero, nullptr, nullptr, pH16,
        CHN, CHN, CHN, HW, 0, sBCHW, sBCHW);

    // 5) S[n,m] = F*[n,:] . SN_t[m,:]   (3 terms; logits)
    f16_gemm_kernel<0, false, 3, false><<<dim3(HW / 128, HW / 128, BATCH), 512, BGK_SMEMB>>>(
        pF, pSNt, nullptr, nullptr, pS, nullptr, CHN, CHN, CHN, HW,
        sBCHW, sBCHW, sBHH);

    // 6) softmax rows of S -> fp16 P
    softmax_kernel<<<BATCH * HW, 256>>>(pS, pP16);

    // 7) O[c,n] = H'[c,:] . P[n,:]   (pure fp16)
    f16_pure_gemm_kernel<<<dim3(HW / 128, CHN / 128, BATCH), 512, PGK_SMEMB>>>(
        pH16, pP16, pO, HW, HW, HW, HW, sBCHW, sBHH, sBCHW);

    // 8) out = O + b*[c] + content
    finaladd_kernel<<<(int)(BATCH * sBCHW / 1024), 256>>>(pO, content, pbs, out);
}

// round 17
// speedup vs baseline: 2.0305x; 1.0224x over previous
#include <cuda_runtime.h>
#include <cuda_fp16.h>
#include <cstdint>
#include <math.h>

#define BATCH 4
#define CHN   512
#define HW    4096
#define EPSF  1e-5f
#define WSZ   (CHN * CHN)

// ---------------- scratch (device globals; no allocations allowed) ----------
__device__ float g_CNt[BATCH * CHN * HW];               // norm(content)^T [b][n][c]
__device__ float g_SNt[BATCH * CHN * HW];               // norm(style)^T   [b][n][c]
__device__ float g_St [BATCH * CHN * HW];               // style^T         [b][n][c]
__device__ float g_F[BATCH * CHN * HW];                 // F* [b][n][c2]
__device__ __half g_H16[BATCH * CHN * HW];              // H' fp16 [b][c][m]
__device__ float g_O0[BATCH * CHN * HW];                // O partial k-half 0
__device__ float g_O1[BATCH * CHN * HW];                // O partial k-half 1
__device__ float g_S[(size_t)BATCH * HW * HW];          // S   [b][n][m]
__device__ __half g_P16[(size_t)BATCH * HW * HW];       // softmax(S) fp16
__device__ float g_WC[2 * WSZ];                         // [Wg^T Wf | Wo Wh]
__device__ float g_w[CHN];                              // Wg^T bf
__device__ float g_bstar[CHN];                          // Wo bh + bo
__device__ float g_zero[CHN];                           // static zeros
__device__ float g_mean[2 * BATCH * CHN];
__device__ float g_rstd[2 * BATCH * CHN];

// ============================ helpers =======================================
__device__ __forceinline__ void mma_f16_f32(float* d, const uint32_t* a, const uint32_t* b) {
    asm volatile(
        "mma.sync.aligned.m16n8k16.row.col.f32.f16.f16.f32 "
        "{%0,%1,%2,%3}, {%4,%5,%6,%7}, {%8,%9}, {%0,%1,%2,%3};"
        : "+f"(d[0]), "+f"(d[1]), "+f"(d[2]), "+f"(d[3])
        : "r"(a[0]), "r"(a[1]), "r"(a[2]), "r"(a[3]), "r"(b[0]), "r"(b[1]));
}

__device__ __forceinline__ void split4(float4 v, uint32_t& h0, uint32_t& h1,
                                       uint32_t& l0, uint32_t& l1) {
    __half2 H0 = __floats2half2_rn(v.x, v.y);
    __half2 H1 = __floats2half2_rn(v.z, v.w);
    float hx = __half2float(__low2half(H0)),  hy = __half2float(__high2half(H0));
    float hz = __half2float(__low2half(H1)),  hw = __half2float(__high2half(H1));
    __half2 L0 = __floats2half2_rn(v.x - hx, v.y - hy);
    __half2 L1 = __floats2half2_rn(v.z - hz, v.w - hw);
    h0 = *(uint32_t*)&H0; h1 = *(uint32_t*)&H1;
    l0 = *(uint32_t*)&L0; l1 = *(uint32_t*)&L1;
}
__device__ __forceinline__ void split4hi(float4 v, uint32_t& h0, uint32_t& h1) {
    __half2 H0 = __floats2half2_rn(v.x, v.y);
    __half2 H1 = __floats2half2_rn(v.z, v.w);
    h0 = *(uint32_t*)&H0; h1 = *(uint32_t*)&H1;
}

// fast exp on the FMA pipe: e^x = 2^(x*log2e), valid for x <= 0
__device__ __forceinline__ float fexp(float x) {
    float t = x * 1.44269504f;
    int n = __float2int_rd(t);
    float f = t - (float)n;
    float p = 1.0f + f * (0.69314718f + f * (0.24022651f + f * (0.05550411f
              + f * (0.00961813f + f * (0.00133336f + f * 0.00015404f)))));
    n = max(n, -127);
    return __int_as_float((uint32_t)(n + 127) << 23) * p;
}

// =================== fp16 split mma GEMM (NT), 512 threads ==================
// (verbatim round-16 kernel)
#define BGK_ROW   20
#define BGK_MAT   (128 * BGK_ROW)
#define BGK_STAGE (4 * BGK_MAT)
#define BGK_SMEMB (2 * BGK_STAGE * 4)            // 81920 bytes

template<int BIASMODE, bool RESID, int TERMS, bool OUTHALF>
__global__ void __launch_bounds__(512, 1)
f16_gemm_kernel(const float* __restrict__ Ag, const float* __restrict__ Bg,
                const float* __restrict__ bias, const float* __restrict__ residg,
                float* __restrict__ Cg, __half* __restrict__ Chg,
                int K, int ldA, int ldB, int ldC,
                size_t sA, size_t sB, size_t sC)
{
    extern __shared__ uint32_t smem_u32[];

    const int t    = threadIdx.x;
    const int lane = t & 31;
    const int wid  = t >> 5;
    const int wm   = wid >> 2;
    const int wn   = wid & 3;
    const int r0   = lane >> 2;
    const int c0   = lane & 3;

    const int b  = blockIdx.z;
    const int m0 = blockIdx.y * 128, n0 = blockIdx.x * 128;
    const float* A = Ag + (size_t)b * sA + (size_t)m0 * ldA;
    const float* B = Bg + (size_t)b * sB + (size_t)n0 * ldB;

    const int NC = K >> 5;
    const int lrow = t >> 2;
    const int lq4  = (t & 3) * 2;

    float4 va[2], vb[2];

    auto gload = [&](int c) {
        const int k0 = c << 5;
        #pragma unroll
        for (int j = 0; j < 2; j++) {
            va[j] = *(const float4*)&A[(size_t)lrow * ldA + k0 + (lq4 + j) * 4];
            vb[j] = *(const float4*)&B[(size_t)lrow * ldB + k0 + (lq4 + j) * 4];
        }
    };
    auto sstore = [&](int s) {
        uint32_t* base = smem_u32 + s * BGK_STAGE;
        #pragma unroll
        for (int j = 0; j < 2; j++) {
            uint32_t off = lrow * BGK_ROW + (lq4 + j) * 2;
            uint32_t h0, h1, l0, l1;
            if (TERMS == 3) {
                split4(va[j], h0, h1, l0, l1);
                base[off] = h0; base[off + 1] = h1;
                base[BGK_MAT + off] = l0; base[BGK_MAT + off + 1] = l1;
            } else {
                split4hi(va[j], h0, h1);
                base[off] = h0; base[off + 1] = h1;
            }
            split4(vb[j], h0, h1, l0, l1);
            base[2 * BGK_MAT + off] = h0; base[2 * BGK_MAT + off + 1] = h1;
            base[3 * BGK_MAT + off] = l0; base[3 * BGK_MAT + off + 1] = l1;
        }
    };

    float acc[2][4][4] = {};

    gload(0);
    sstore(0);
    if (NC > 1) gload(1);
    __syncthreads();

    for (int c = 0; c < NC; c++) {
        const int s = c & 1;
        const uint32_t* sa_h = smem_u32 + s * BGK_STAGE;
        const uint32_t* sa_l = sa_h + BGK_MAT;
        const uint32_t* sb_h = sa_h + 2 * BGK_MAT;
        const uint32_t* sb_l = sa_h + 3 * BGK_MAT;

        #pragma unroll
        for (int kk = 0; kk < 2; kk++) {
            uint32_t ah[2][4], al[2][4], bh[4][2], bl[4][2];
            const int cA = kk * 8 + c0;
            #pragma unroll
            for (int mt = 0; mt < 2; mt++) {
                int r = wm * 32 + mt * 16 + r0;
                const uint32_t* ph = &sa_h[r * BGK_ROW + cA];
                ah[mt][0] = ph[0]; ah[mt][1] = ph[8 * BGK_ROW];
                ah[mt][2] = ph[4]; ah[mt][3] = ph[8 * BGK_ROW + 4];
                if (TERMS == 3) {
                    const uint32_t* pl = &sa_l[r * BGK_ROW + cA];
                    al[mt][0] = pl[0]; al[mt][1] = pl[8 * BGK_ROW];
                    al[mt][2] = pl[4]; al[mt][3] = pl[8 * BGK_ROW + 4];
                }
            }
            #pragma unroll
            for (int nt = 0; nt < 4; nt++) {
                int n = wn * 32 + nt * 8 + r0;
                bh[nt][0] = sb_h[n * BGK_ROW + cA]; bh[nt][1] = sb_h[n * BGK_ROW + cA + 4];
                bl[nt][0] = sb_l[n * BGK_ROW + cA]; bl[nt][1] = sb_l[n * BGK_ROW + cA + 4];
            }

            if (kk == 0) { if (c + 1 < NC) sstore((c + 1) & 1); }
            else         { if (c + 2 < NC) gload(c + 2); }

            #pragma unroll
            for (int mt = 0; mt < 2; mt++)
                #pragma unroll
                for (int nt = 0; nt < 4; nt++)
                    mma_f16_f32(acc[mt][nt], ah[mt], bh[nt]);
            #pragma unroll
            for (int mt = 0; mt < 2; mt++)
                #pragma unroll
                for (int nt = 0; nt < 4; nt++)
                    mma_f16_f32(acc[mt][nt], ah[mt], bl[nt]);
            if (TERMS == 3) {
                #pragma unroll
                for (int mt = 0; mt < 2; mt++)
                    #pragma unroll
                    for (int nt = 0; nt < 4; nt++)
                        mma_f16_f32(acc[mt][nt], al[mt], bh[nt]);
            }
        }
        __syncthreads();
    }

    // ---- epilogue ----
    #pragma unroll
    for (int mt = 0; mt < 2; mt++) {
        int row = m0 + wm * 32 + mt * 16 + r0;
        float br0 = 0.f, br1 = 0.f;
        if (BIASMODE == 1) { br0 = bias[row]; br1 = bias[row + 8]; }
        #pragma unroll
        for (int nt = 0; nt < 4; nt++) {
            int col = n0 + wn * 32 + nt * 8 + c0 * 2;
            float2 v0 = make_float2(acc[mt][nt][0], acc[mt][nt][1]);
            float2 v1 = make_float2(acc[mt][nt][2], acc[mt][nt][3]);
            if (BIASMODE == 1) {
                v0.x += br0; v0.y += br0;
                v1.x += br1; v1.y += br1;
            } else if (BIASMODE == 2) {
                float bx = bias[col], by = bias[col + 1];
                v0.x += bx; v0.y += by;
                v1.x += bx; v1.y += by;
            }
            size_t o0 = (size_t)b * sC + (size_t)row * ldC + col;
            size_t o1 = (size_t)b * sC + (size_t)(row + 8) * ldC + col;
            if (OUTHALF) {
                *(__half2*)&Chg[o0] = __floats2half2_rn(v0.x, v0.y);
                *(__half2*)&Chg[o1] = __floats2half2_rn(v1.x, v1.y);
            } else {
                if (RESID) {
                    float2 rv0 = *(const float2*)&residg[o0];
                    float2 rv1 = *(const float2*)&residg[o1];
                    v0.x += rv0.x; v0.y += rv0.y;
                    v1.x += rv1.x; v1.y += rv1.y;
                }
                *(float2*)&Cg[o0] = v0;
                *(float2*)&Cg[o1] = v1;
            }
        }
    }
}

// ====== pure fp16 GEMM (NT), split-K=2 single launch, 512 threads ===========
// grid (N/128, 2*M/128, BATCH): blockIdx.y = ks*(M/128) + mtile, M/128 == 4.
// ks selects k-half [ks*Khalf, (ks+1)*Khalf) and output buffer C0/C1.
#define PGK_MAT   (128 * BGK_ROW)
#define PGK_STAGE (2 * PGK_MAT)
#define PGK_SMEMB (2 * PGK_STAGE * 4)            // 40960 bytes

__global__ void __launch_bounds__(512, 1)
f16_pure_gemm_splitk(const __half* __restrict__ Ag, const __half* __restrict__ Bg,
                     float* __restrict__ C0g, float* __restrict__ C1g,
                     int Khalf, int ldA, int ldB, int ldC,
                     size_t sA, size_t sB, size_t sC)
{
    extern __shared__ uint32_t smem_u32[];

    const int t    = threadIdx.x;
    const int lane = t & 31;
    const int wid  = t >> 5;
    const int wm   = wid >> 2;
    const int wn   = wid & 3;
    const int r0   = lane >> 2;
    const int c0   = lane & 3;

    const int b  = blockIdx.z;
    const int ks = blockIdx.y >> 2;                    // 0 or 1
    const int m0 = (blockIdx.y & 3) * 128;
    const int n0 = blockIdx.x * 128;
    const __half* A = Ag + (size_t)b * sA + (size_t)m0 * ldA + (size_t)ks * Khalf;
    const __half* B = Bg + (size_t)b * sB + (size_t)n0 * ldB + (size_t)ks * Khalf;
    float*        C = (ks ? C1g : C0g) + (size_t)b * sC;

    const int NC = Khalf >> 5;
    const int lrow = t >> 2;
    const int lq   = t & 3;

    uint4 ua, ub;
    auto gload = [&](int c) {
        const int k0 = c << 5;
        ua = *(const uint4*)&A[(size_t)lrow * ldA + k0 + lq * 8];
        ub = *(const uint4*)&B[(size_t)lrow * ldB + k0 + lq * 8];
    };
    auto sstore = [&](int s) {
        uint32_t* base = smem_u32 + s * PGK_STAGE;
        *(uint4*)&base[lrow * BGK_ROW + lq * 4] = ua;
        *(uint4*)&base[PGK_MAT + lrow * BGK_ROW + lq * 4] = ub;
    };

    float acc[2][4][4] = {};

    gload(0);
    sstore(0);
    if (NC > 1) gload(1);
    __syncthreads();

    for (int c = 0; c < NC; c++) {
        const int s = c & 1;
        const uint32_t* sa = smem_u32 + s * PGK_STAGE;
        const uint32_t* sb = sa + PGK_MAT;

        #pragma unroll
        for (int kk = 0; kk < 2; kk++) {
            uint32_t ah[2][4], bh[4][2];
            const int cA = kk * 8 + c0;
            #pragma unroll
            for (int mt = 0; mt < 2; mt++) {
                int r = wm * 32 + mt * 16 + r0;
                const uint32_t* ph = &sa[r * BGK_ROW + cA];
                ah[mt][0] = ph[0]; ah[mt][1] = ph[8 * BGK_ROW];
                ah[mt][2] = ph[4]; ah[mt][3] = ph[8 * BGK_ROW + 4];
            }
            #pragma unroll
            for (int nt = 0; nt < 4; nt++) {
                int n = wn * 32 + nt * 8 + r0;
                bh[nt][0] = sb[n * BGK_ROW + cA]; bh[nt][1] = sb[n * BGK_ROW + cA + 4];
            }

            if (kk == 0) { if (c + 1 < NC) sstore((c + 1) & 1); }
            else         { if (c + 2 < NC) gload(c + 2); }

            #pragma unroll
            for (int mt = 0; mt < 2; mt++)
                #pragma unroll
                for (int nt = 0; nt < 4; nt++)
                    mma_f16_f32(acc[mt][nt], ah[mt], bh[nt]);
        }
        __syncthreads();
    }

    #pragma unroll
    for (int mt = 0; mt < 2; mt++) {
        int row = m0 + wm * 32 + mt * 16 + r0;
        #pragma unroll
        for (int nt = 0; nt < 4; nt++) {
            int col = n0 + wn * 32 + nt * 8 + c0 * 2;
            *(float2*)&C[(size_t)row * ldC + col] =
                make_float2(acc[mt][nt][0], acc[mt][nt][1]);
            *(float2*)&C[(size_t)(row + 8) * ldC + col] =
                make_float2(acc[mt][nt][2], acc[mt][nt][3]);
        }
    }
}

// -------- WC0 = Wg^T Wf ; WC1 = Wo Wh  (simple exact fp32 SIMT GEMM) --------
__global__ void __launch_bounds__(256)
wcomb_kernel(const float* __restrict__ Wf, const float* __restrict__ Wg,
             const float* __restrict__ Wh, const float* __restrict__ Wo,
             float* __restrict__ WC)
{
    const int mode = blockIdx.z;                 // 0: Wg^T Wf, 1: Wo Wh
    const int m0 = blockIdx.y * 64, n0 = blockIdx.x * 64;
    const int t = threadIdx.x;
    const int tx = t & 15, ty = t >> 4;

    __shared__ float As[16][65], Bs[16][65];
    const float* A = (mode == 0) ? Wg : Wo;
    const float* Bsrc = (mode == 0) ? Wf : Wh;

    float acc[4][4] = {};

    for (int k0 = 0; k0 < CHN; k0 += 16) {
        #pragma unroll
        for (int i = 0; i < 4; i++) {
            int idx = t + i * 256;
            int kk = idx >> 6, mm = idx & 63;
            As[kk][mm] = (mode == 0)
                ? A[(size_t)(k0 + kk) * CHN + m0 + mm]
                : A[(size_t)(m0 + mm) * CHN + k0 + kk];
            Bs[kk][mm] = Bsrc[(size_t)(k0 + kk) * CHN + n0 + mm];
        }
        __syncthreads();
        #pragma unroll
        for (int kk = 0; kk < 16; kk++) {
            float ar[4], br[4];
            #pragma unroll
            for (int i = 0; i < 4; i++) ar[i] = As[kk][ty * 4 + i];
            #pragma unroll
            for (int j = 0; j < 4; j++) br[j] = Bs[kk][tx * 4 + j];
            #pragma unroll
            for (int i = 0; i < 4; i++)
                #pragma unroll
                for (int j = 0; j < 4; j++)
                    acc[i][j] = fmaf(ar[i], br[j], acc[i][j]);
        }
        __syncthreads();
    }

    #pragma unroll
    for (int i = 0; i < 4; i++) {
        size_t o = (size_t)mode * WSZ + (size_t)(m0 + ty * 4 + i) * CHN + n0 + tx * 4;
        *(float4*)&WC[o] = make_float4(acc[i][0], acc[i][1], acc[i][2], acc[i][3]);
    }
}

// -------- w = Wg^T bf ; b* = Wo bh + bo  (parallelized) ---------------------
__global__ void __launch_bounds__(64)
vec_kernel(const float* __restrict__ Wg, const float* __restrict__ Wo,
           const float* __restrict__ bf, const float* __restrict__ bh,
           const float* __restrict__ bo,
           float* __restrict__ w, float* __restrict__ bstar)
{
    int c = blockIdx.x * 64 + threadIdx.x;
    if (blockIdx.y == 0) {
        float s = 0.f;
        for (int k = 0; k < CHN; k++) s += Wg[(size_t)k * CHN + c] * bf[k];
        w[c] = s;
    } else {
        float s = 0.f;
        for (int k = 0; k < CHN; k++) s += Wo[(size_t)c * CHN + k] * bh[k];
        bstar[c] = s + bo[c];
    }
}

// -------- out = O0 + O1 + b*[c] + content  ----------------------------------
__global__ void __launch_bounds__(256)
finaladd_kernel(const float* __restrict__ O0, const float* __restrict__ O1,
                const float* __restrict__ content,
                const float* __restrict__ bstar, float* __restrict__ out)
{
    size_t i = ((size_t)blockIdx.x * 256 + threadIdx.x) * 4;
    int c = (int)((i / HW) % CHN);
    float bv = bstar[c];
    float4 a = *(const float4*)&O0[i];
    float4 d = *(const float4*)&O1[i];
    float4 r = *(const float4*)&content[i];
    a.x += d.x + bv + r.x; a.y += d.y + bv + r.y;
    a.z += d.z + bv + r.z; a.w += d.w + bv + r.w;
    *(float4*)&out[i] = a;
}

// ---------------- per-(b,c) mean / rstd over 4096 spatial elems -------------
__global__ void __launch_bounds__(256)
stats_kernel(const float* __restrict__ content, const float* __restrict__ style)
{
    int bc  = blockIdx.x;
    int sel = blockIdx.y;
    const float* x = (sel == 0 ? content : style) + (size_t)bc * HW;

    float s1 = 0.f, s2 = 0.f;
    for (int i = threadIdx.x * 4; i < HW; i += 256 * 4) {
        float4 v = *(const float4*)&x[i];
        s1 += v.x + v.y + v.z + v.w;
        s2 += v.x * v.x + v.y * v.y + v.z * v.z + v.w * v.w;
    }
    __shared__ float sh1[8], sh2[8];
    for (int o = 16; o > 0; o >>= 1) {
        s1 += __shfl_xor_sync(0xffffffffu, s1, o);
        s2 += __shfl_xor_sync(0xffffffffu, s2, o);
    }
    int warp = threadIdx.x >> 5, lane = threadIdx.x & 31;
    if (lane == 0) { sh1[warp] = s1; sh2[warp] = s2; }
    __syncthreads();
    if (threadIdx.x < 32) {
        s1 = (lane < 8) ? sh1[lane] : 0.f;
        s2 = (lane < 8) ? sh2[lane] : 0.f;
        for (int o = 4; o > 0; o >>= 1) {
            s1 += __shfl_xor_sync(0xffffffffu, s1, o);
            s2 += __shfl_xor_sync(0xffffffffu, s2, o);
        }
        if (lane == 0) {
            float mean = s1 / (float)HW;
            float var  = (s2 - s1 * mean) / (float)(HW - 1);
            int idx = sel * BATCH * CHN + bc;
            g_mean[idx] = mean;
            g_rstd[idx] = rsqrtf(var + EPSF);
        }
    }
}

// ------- transpose + normalize: [b][c][n] -> [b][n][c], 3 outputs ----------
__global__ void __launch_bounds__(256)
transnorm_kernel(const float* __restrict__ content, const float* __restrict__ style,
                 float* __restrict__ CNt, float* __restrict__ SNt,
                 float* __restrict__ St)
{
    __shared__ float tc[32][33], ts[32][33];
    int b  = blockIdx.z;
    int c0 = blockIdx.y * 32, n0 = blockIdx.x * 32;
    int t  = threadIdx.x;
    int r  = t >> 3, q = (t & 7) * 4;

    size_t ib = (size_t)b * CHN * HW + (size_t)(c0 + r) * HW + n0 + q;
    float mC = g_mean[b * CHN + c0 + r], rC = g_rstd[b * CHN + c0 + r];
    float4 v = *(const float4*)&content[ib];
    tc[r][q + 0] = (v.x - mC) * rC; tc[r][q + 1] = (v.y - mC) * rC;
    tc[r][q + 2] = (v.z - mC) * rC; tc[r][q + 3] = (v.w - mC) * rC;
    float4 w = *(const float4*)&style[ib];
    ts[r][q + 0] = w.x; ts[r][q + 1] = w.y; ts[r][q + 2] = w.z; ts[r][q + 3] = w.w;
    __syncthreads();

    size_t ob = (size_t)b * CHN * HW + (size_t)(n0 + r) * CHN + c0 + q;
    float4 o;
    o.x = tc[q + 0][r]; o.y = tc[q + 1][r]; o.z = tc[q + 2][r]; o.w = tc[q + 3][r];
    *(float4*)&CNt[ob] = o;

    float4 sraw;
    sraw.x = ts[q + 0][r]; sraw.y = ts[q + 1][r];
    sraw.z = ts[q + 2][r]; sraw.w = ts[q + 3][r];
    *(float4*)&St[ob] = sraw;

    int sidx = BATCH * CHN + b * CHN + c0 + q;
    float4 sm = *(const float4*)&g_mean[sidx];
    float4 sr = *(const float4*)&g_rstd[sidx];
    float4 sn;
    sn.x = (sraw.x - sm.x) * sr.x; sn.y = (sraw.y - sm.y) * sr.y;
    sn.z = (sraw.z - sm.z) * sr.z; sn.w = (sraw.w - sm.w) * sr.w;
    *(float4*)&SNt[ob] = sn;
}

// ------- row softmax over 4096, fp16 output, FMA-pipe exp -------------------
__global__ void __launch_bounds__(256)
softmax_kernel(const float* __restrict__ S, __half* __restrict__ P16)
{
    __shared__ float buf[HW];
    __shared__ float red1[8], red2[8];
    const float* p = S + (size_t)blockIdx.x * HW;
    __half* po = P16 + (size_t)blockIdx.x * HW;
    int t = threadIdx.x, lane = t & 31, warp = t >> 5;

    float m = -3.4e38f;
    for (int i = t * 4; i < HW; i += 1024) {
        float4 v = *(const float4*)&p[i];
        *(float4*)&buf[i] = v;
        m = fmaxf(m, fmaxf(fmaxf(v.x, v.y), fmaxf(v.z, v.w)));
    }
    for (int o = 16; o > 0; o >>= 1) m = fmaxf(m, __shfl_xor_sync(0xffffffffu, m, o));
    if (lane == 0) red1[warp] = m;
    __syncthreads();
    if (t < 32) {
        m = (lane < 8) ? red1[lane] : -3.4e38f;
        for (int o = 4; o > 0; o >>= 1) m = fmaxf(m, __shfl_xor_sync(0xffffffffu, m, o));
        if (lane == 0) red1[0] = m;
    }
    __syncthreads();
    m = red1[0];

    float s = 0.f;
    for (int i = t * 4; i < HW; i += 1024) {
        float4 v = *(const float4*)&buf[i];
        v.x = fexp(v.x - m); v.y = fexp(v.y - m);
        v.z = fexp(v.z - m); v.w = fexp(v.w - m);
        *(float4*)&buf[i] = v;
        s += v.x + v.y + v.z + v.w;
    }
    for (int o = 16; o > 0; o >>= 1) s += __shfl_xor_sync(0xffffffffu, s, o);
    if (lane == 0) red2[warp] = s;
    __syncthreads();
    if (t < 32) {
        s = (lane < 8) ? red2[lane] : 0.f;
        for (int o = 4; o > 0; o >>= 1) s += __shfl_xor_sync(0xffffffffu, s, o);
        if (lane == 0) red2[0] = s;
    }
    __syncthreads();
    float inv = 1.0f / red2[0];
    for (int i = t * 4; i < HW; i += 1024) {
        float4 v = *(const float4*)&buf[i];
        *(__half2*)&po[i]     = __floats2half2_rn(v.x * inv, v.y * inv);
        *(__half2*)&po[i + 2] = __floats2half2_rn(v.z * inv, v.w * inv);
    }
}

// ---------------- launch --------------------------------------------------
extern "C" void kernel_launch(void* const* d_in, const int* in_sizes, int n_in,
                              void* d_out, int out_size)
{
    const float* content = (const float*)d_in[0];
    const float* style   = (const float*)d_in[1];
    const float* Wf = (const float*)d_in[2]; const float* bf = (const float*)d_in[3];
    const float* Wg = (const float*)d_in[4]; const float* bg = (const float*)d_in[5];
    const float* Wh = (const float*)d_in[6]; const float* bh = (const float*)d_in[7];
    const float* Wo = (const float*)d_in[8]; const float* bo = (const float*)d_in[9];
    float* out = (float*)d_out;
    (void)bg;   // cancels under softmax shift-invariance

    float *pCNt, *pSNt, *pSt, *pF, *pO0, *pO1, *pS, *pWC, *pw, *pbs, *pzero;
    __half *pH16, *pP16;
    cudaGetSymbolAddress((void**)&pCNt, g_CNt);
    cudaGetSymbolAddress((void**)&pSNt, g_SNt);
    cudaGetSymbolAddress((void**)&pSt,  g_St);
    cudaGetSymbolAddress((void**)&pF,   g_F);
    cudaGetSymbolAddress((void**)&pH16, g_H16);
    cudaGetSymbolAddress((void**)&pO0,  g_O0);
    cudaGetSymbolAddress((void**)&pO1,  g_O1);
    cudaGetSymbolAddress((void**)&pS,   g_S);
    cudaGetSymbolAddress((void**)&pP16, g_P16);
    cudaGetSymbolAddress((void**)&pWC,  g_WC);
    cudaGetSymbolAddress((void**)&pw,   g_w);
    cudaGetSymbolAddress((void**)&pbs,  g_bstar);
    cudaGetSymbolAddress((void**)&pzero, g_zero);

    cudaFuncSetAttribute(f16_gemm_kernel<2, false, 3, false>,
                         cudaFuncAttributeMaxDynamicSharedMemorySize, BGK_SMEMB);
    cudaFuncSetAttribute(f16_gemm_kernel<1, false, 2, true>,
                         cudaFuncAttributeMaxDynamicSharedMemorySize, BGK_SMEMB);
    cudaFuncSetAttribute(f16_gemm_kernel<0, false, 3, false>,
                         cudaFuncAttributeMaxDynamicSharedMemorySize, BGK_SMEMB);
    cudaFuncSetAttribute(f16_pure_gemm_splitk,
                         cudaFuncAttributeMaxDynamicSharedMemorySize, PGK_SMEMB);

    const size_t sBCHW = (size_t)CHN * HW;
    const size_t sBHH  = (size_t)HW * HW;

    // 1) stats + combined weights + vectors
    stats_kernel<<<dim3(BATCH * CHN, 2), 256>>>(content, style);
    wcomb_kernel<<<dim3(8, 8, 2), 256>>>(Wf, Wg, Wh, Wo, pWC);
    vec_kernel<<<dim3(8, 2), 64>>>(Wg, Wo, bf, bh, bo, pw, pbs);

    // 2) transpose + normalize
    transnorm_kernel<<<dim3(HW / 32, CHN / 32, BATCH), 256>>>(
        content, style, pCNt, pSNt, pSt);

    // 3) F*[n,c2] = CN_t[n,:] . WC0[c2,:] + w[c2]   (3 terms)
    f16_gemm_kernel<2, false, 3, false><<<dim3(CHN / 128, HW / 128, BATCH), 512, BGK_SMEMB>>>(
        pCNt, pWC, pw, nullptr, pF, nullptr, CHN, CHN, CHN, CHN, sBCHW, 0, sBCHW);

    // 4) H'[c,m] = WC1[c,:] . St[m,:]   (2 terms; zero bias; fp16 out)
    f16_gemm_kernel<1, false, 2, true><<<dim3(HW / 128, CHN / 128, BATCH), 512, BGK_SMEMB>>>(
        pWC + WSZ, pSt, pzero, nullptr, nullptr, pH16,
        CHN, CHN, CHN, HW, 0, sBCHW, sBCHW);

    // 5) S[n,m] = F*[n,:] . SN_t[m,:]   (3 terms; logits)
    f16_gemm_kernel<0, false, 3, false><<<dim3(HW / 128, HW / 128, BATCH), 512, BGK_SMEMB>>>(
        pF, pSNt, nullptr, nullptr, pS, nullptr, CHN, CHN, CHN, HW,
        sBCHW, sBCHW, sBHH);

    // 6) softmax rows of S -> fp16 P
    softmax_kernel<<<BATCH * HW, 256>>>(pS, pP16);

    // 7) O = H' . P^T, split-K=2 single launch (1024 CTAs -> 7 waves)
    f16_pure_gemm_splitk<<<dim3(HW / 128, 2 * CHN / 128, BATCH), 512, PGK_SMEMB>>>(
        pH16, pP16, pO0, pO1, HW / 2, HW, HW, HW, sBCHW, sBHH, sBCHW);

    // 8) out = O0 + O1 + b*[c] + content
    finaladd_kernel<<<(int)(BATCH * sBCHW / 1024), 256>>>(pO0, pO1, content, pbs, out);
}